// round 6
// baseline (speedup 1.0000x reference)
#include <cuda_runtime.h>
#include <math.h>

// ---------------------------------------------------------------------------
// Problem constants
// ---------------------------------------------------------------------------
#define BB    8
#define CIN   128
#define COUT  128
#define KK3   3
#define KN    4
#define HH    160
#define WW    160
#define ATT   16
#define MID   32
#define HW    (HH*WW)          // 25600
#define IKK   (CIN*9)          // 1152
#define PB    (2*BB)           // 16 (path, batch) combos

// ---------------------------------------------------------------------------
// Scratch (static device globals; no runtime allocation)
// ---------------------------------------------------------------------------
__device__ float g_gap0[BB*CIN];
__device__ float g_gap1[BB*CIN];
__device__ float g_fdmean[BB*CIN];
__device__ float g_fdmax[BB*CIN];

__device__ float g_ca[PB*CIN];     // [p*8+b][cin]   input-channel attention
__device__ float g_fa[PB*COUT];    // [pb][cout]     filter attention
__device__ float g_sM[PB*9];       // [pb][kk]       sa * Mfd
__device__ float g_ka[PB*KN];      // [pb][n]        kernel softmax

__device__ float g_A[PB*COUT*IKK];    // fa-folded, ka-mixed weights  [pb][c][ikk]
__device__ float g_WfT[PB*IKK*COUT];  // final folded weights         [pb][ikk][o]

__device__ __forceinline__ float sigm(float x){ return 1.f/(1.f+expf(-x)); }

// ---- packed f32x2 helpers (Blackwell FFMA2 path) --------------------------
__device__ __forceinline__ unsigned long long pack2(float lo, float hi){
    unsigned long long r;
    asm("mov.b64 %0, {%1, %2};" : "=l"(r) : "f"(lo), "f"(hi));
    return r;
}
__device__ __forceinline__ unsigned long long ffma2(unsigned long long a,
                                                    unsigned long long b,
                                                    unsigned long long c){
    unsigned long long d;
    asm("fma.rn.f32x2 %0, %1, %2, %3;" : "=l"(d) : "l"(a), "l"(b), "l"(c));
    return d;
}
__device__ __forceinline__ float2 unpack2(unsigned long long v){
    float lo, hi;
    asm("mov.b64 {%0, %1}, %2;" : "=f"(lo), "=f"(hi) : "l"(v));
    return make_float2(lo, hi);
}

// ---------------------------------------------------------------------------
// Kernel 1: per-(b,c) plane reductions: mean(x0), mean(x1), max(x0-x1)
// ---------------------------------------------------------------------------
__global__ __launch_bounds__(256) void k_stats(const float* __restrict__ x0,
                                               const float* __restrict__ x1){
    int bc = blockIdx.x;                         // 0..1023
    const float4* p0 = (const float4*)(x0 + (size_t)bc*HW);
    const float4* p1 = (const float4*)(x1 + (size_t)bc*HW);
    float s0=0.f, s1=0.f, mx=-3.0e38f;
    for (int i = threadIdx.x; i < HW/4; i += 256){
        float4 a = p0[i], b = p1[i];
        s0 += (a.x+a.y)+(a.z+a.w);
        s1 += (b.x+b.y)+(b.z+b.w);
        float d0 = a.x-b.x, d1 = a.y-b.y, d2 = a.z-b.z, d3 = a.w-b.w;
        mx = fmaxf(mx, fmaxf(fmaxf(d0,d1), fmaxf(d2,d3)));
    }
    #pragma unroll
    for (int off=16; off; off>>=1){
        s0 += __shfl_down_sync(0xffffffffu, s0, off);
        s1 += __shfl_down_sync(0xffffffffu, s1, off);
        mx  = fmaxf(mx, __shfl_down_sync(0xffffffffu, mx, off));
    }
    __shared__ float r0[8], r1[8], rm[8];
    int w = threadIdx.x >> 5;
    if ((threadIdx.x & 31) == 0){ r0[w]=s0; r1[w]=s1; rm[w]=mx; }
    __syncthreads();
    if (threadIdx.x == 0){
        float S0=0.f, S1=0.f, M=-3.0e38f;
        #pragma unroll
        for (int i=0;i<8;++i){ S0+=r0[i]; S1+=r1[i]; M=fmaxf(M, rm[i]); }
        const float inv = 1.f/(float)HW;
        g_gap0[bc]   = S0*inv;
        g_gap1[bc]   = S1*inv;
        g_fdmean[bc] = (S0-S1)*inv;
        g_fdmax[bc]  = M;
    }
}

// ---------------------------------------------------------------------------
// Kernel 2: attention + dif_atten (one block per batch, 128 threads)
// ---------------------------------------------------------------------------
__global__ __launch_bounds__(128) void k_att(
    const float* __restrict__ fc_w,  const float* __restrict__ ln_g,  const float* __restrict__ ln_b,
    const float* __restrict__ ch_w,  const float* __restrict__ ch_b,
    const float* __restrict__ fl_w,  const float* __restrict__ fl_b,
    const float* __restrict__ sp_w,  const float* __restrict__ sp_b,
    const float* __restrict__ kn_w,  const float* __restrict__ kn_b,
    const float* __restrict__ mlp_w1,const float* __restrict__ mlp_b1,
    const float* __restrict__ mlp_w2,const float* __restrict__ mlp_b2)
{
    int b = blockIdx.x, tid = threadIdx.x;
    __shared__ float gA[128], gB[128], yv[ATT], hs[MID], mfd[9], kl[KN];

    // ---- Mfd (shared across both paths) ----
    gA[tid] = g_fdmean[b*CIN + tid];
    gB[tid] = g_fdmax [b*CIN + tid];
    __syncthreads();
    if (tid < MID){
        float sa_ = mlp_b1[tid], sm_ = mlp_b1[tid];
        for (int c=0;c<CIN;++c){ float w = mlp_w1[tid*CIN+c]; sa_ += w*gA[c]; sm_ += w*gB[c]; }
        hs[tid] = fmaxf(sa_,0.f) + fmaxf(sm_,0.f);
    }
    __syncthreads();
    if (tid < 9){
        float z = 2.f*mlp_b2[tid];
        for (int t=0;t<MID;++t) z += mlp_w2[tid*MID+t]*hs[t];
        mfd[tid] = sigm(z);
    }

    // ---- attention per path ----
    for (int p=0;p<2;++p){
        __syncthreads();
        gA[tid] = (p ? g_gap1 : g_gap0)[b*CIN + tid];
        __syncthreads();
        if (tid < ATT){
            float v = 0.f;
            for (int c=0;c<CIN;++c) v += fc_w[tid*CIN+c]*gA[c];
            yv[tid] = v;
        }
        __syncthreads();
        if (tid == 0){
            float mu = 0.f;
            for (int j=0;j<ATT;++j) mu += yv[j];
            mu *= (1.f/ATT);
            float var = 0.f;
            for (int j=0;j<ATT;++j){ float d = yv[j]-mu; var += d*d; }
            var *= (1.f/ATT);
            float inv = rsqrtf(var + 1e-5f);
            for (int j=0;j<ATT;++j)
                yv[j] = fmaxf(0.f, (yv[j]-mu)*inv*ln_g[j] + ln_b[j]);
        }
        __syncthreads();
        {
            float ac = ch_b[tid], af = fl_b[tid];
            for (int j=0;j<ATT;++j){ ac += ch_w[tid*ATT+j]*yv[j]; af += fl_w[tid*ATT+j]*yv[j]; }
            g_ca[(p*BB+b)*CIN  + tid] = sigm(ac);
            g_fa[(p*BB+b)*COUT + tid] = sigm(af);
        }
        if (tid < 9){
            float s = sp_b[tid];
            for (int j=0;j<ATT;++j) s += sp_w[tid*ATT+j]*yv[j];
            g_sM[(p*BB+b)*9 + tid] = sigm(s)*mfd[tid];
        }
        if (tid < KN){
            float l = kn_b[tid];
            for (int j=0;j<ATT;++j) l += kn_w[tid*ATT+j]*yv[j];
            kl[tid] = l;
        }
        __syncthreads();
        if (tid == 0){
            float m = fmaxf(fmaxf(kl[0],kl[1]), fmaxf(kl[2],kl[3]));
            float e0=expf(kl[0]-m), e1=expf(kl[1]-m), e2=expf(kl[2]-m), e3=expf(kl[3]-m);
            float s = e0+e1+e2+e3;
            g_ka[(p*BB+b)*KN+0] = e0/s; g_ka[(p*BB+b)*KN+1] = e1/s;
            g_ka[(p*BB+b)*KN+2] = e2/s; g_ka[(p*BB+b)*KN+3] = e3/s;
        }
    }
}

// ---------------------------------------------------------------------------
// Kernel 3a: A[pb][c][ikk] = fa[pb][c] * sum_n ka[pb][n]*weight[n][c][ikk]
// ---------------------------------------------------------------------------
__global__ __launch_bounds__(256) void k_agg(const float* __restrict__ weight){
    int pb  = blockIdx.y;
    int idx = blockIdx.x*256 + threadIdx.x;   // < 128*1152 = 147456
    int c   = idx / IKK;
    float k0 = g_ka[pb*KN+0], k1 = g_ka[pb*KN+1], k2 = g_ka[pb*KN+2], k3 = g_ka[pb*KN+3];
    const float* w = weight + idx;            // weight[(n*128+c)*1152+ikk] = weight[n*147456 + idx]
    float acc = k0*w[0] + k1*w[COUT*IKK] + k2*w[2*COUT*IKK] + k3*w[3*COUT*IKK];
    g_A[pb*(COUT*IKK) + idx] = acc * g_fa[pb*COUT + c];
}

// ---------------------------------------------------------------------------
// Kernel 3b: WfT[pb][ikk][o] = ca[i]*sM[kk] * sum_c fuse_w[o, p*128+c]*A[pb][c][ikk]
//   GEMM M=128(o) x N=64(ikk tile) x K=128(c);  grid (18 ntiles, 16 pb)
// ---------------------------------------------------------------------------
__global__ __launch_bounds__(256) void k_wf(const float* __restrict__ fuse_w){
    int pb = blockIdx.y, p = pb >> 3;
    int nt = blockIdx.x;
    int tid = threadIdx.x;
    int to = tid & 15;        // o-group: o = to*8 .. to*8+7
    int tn = tid >> 4;        // ikk-group: nn = tn*4 .. tn*4+3
    __shared__ __align__(16) float Fs[16][128];
    __shared__ __align__(16) float As[16][64];
    float acc[8][4];
    #pragma unroll
    for (int o=0;o<8;++o)
        #pragma unroll
        for (int n=0;n<4;++n) acc[o][n]=0.f;

    const float* Abase = g_A + (size_t)pb*(COUT*IKK);
    for (int ck=0; ck<8; ++ck){
        __syncthreads();
        #pragma unroll
        for (int j=0;j<8;++j){          // 2048 fuse elements
            int l = j*256 + tid; int o = l & 127, cc = l >> 7;
            Fs[cc][o] = fuse_w[o*(2*COUT) + p*COUT + ck*16 + cc];
        }
        #pragma unroll
        for (int j=0;j<4;++j){          // 1024 A elements
            int l = j*256 + tid; int nn = l & 63, cc = l >> 6;
            As[cc][nn] = Abase[(ck*16+cc)*IKK + nt*64 + nn];
        }
        __syncthreads();
        #pragma unroll
        for (int cc=0; cc<16; ++cc){
            float4 av = *(const float4*)&As[cc][tn*4];
            float a_[4] = {av.x, av.y, av.z, av.w};
            float4 f0 = *(const float4*)&Fs[cc][to*8];
            float4 f1 = *(const float4*)&Fs[cc][to*8+4];
            float f_[8] = {f0.x,f0.y,f0.z,f0.w, f1.x,f1.y,f1.z,f1.w};
            #pragma unroll
            for (int o=0;o<8;++o)
                #pragma unroll
                for (int n=0;n<4;++n)
                    acc[o][n] = fmaf(f_[o], a_[n], acc[o][n]);
        }
    }
    float* Wbase = g_WfT + (size_t)pb*(IKK*COUT);
    const float* cap = g_ca + pb*CIN;
    const float* sMp = g_sM + pb*9;
    #pragma unroll
    for (int n=0;n<4;++n){
        int ikk = nt*64 + tn*4 + n;
        int i = ikk/9, kk = ikk - i*9;
        float sc = cap[i]*sMp[kk];
        #pragma unroll
        for (int o=0;o<8;++o)
            Wbase[ikk*COUT + to*8 + o] = acc[o][n]*sc;
    }
}

// ---------------------------------------------------------------------------
// Kernel 4: direct 3x3 conv via packed FFMA2, both paths summed, + fuse bias.
//   Block: 256 thr, tile = 64 out-ch x (8y x 32x), thread = 8 oc x 8 px.
//   oc handled as 4 packed pairs (f32x2 lanes). Grid: (100, 2, 8)
//   sInp row stride 35: compute-read bank = (3*qy + 8*qx) mod 32 -> conflict-free.
// ---------------------------------------------------------------------------
__global__ __launch_bounds__(256) void k_conv(const float* __restrict__ x0,
                                              const float* __restrict__ x1,
                                              const float* __restrict__ fuse_b,
                                              float* __restrict__ out){
    int b = blockIdx.z, octile = blockIdx.y;
    int tile = blockIdx.x;
    int txl = tile % 5, tyl = tile / 5;
    int xbase = txl*32, ybase = tyl*8;
    int tid = threadIdx.x;
    int q  = tid & 31, og = tid >> 5;
    int qy = q >> 2,  qx = q & 3;          // 8 rows x 4 col-groups (8 px each)

    __shared__ float sInp[8][10][35];              // 8 ic, 10 rows, 34 used cols (stride 35)
    __shared__ __align__(16) float sW[8][9][64];   // 8 ic, 9 taps, 64 oc

    unsigned long long acc2[4][8];                 // [oc-pair][pixel j]
    #pragma unroll
    for (int o2=0;o2<4;++o2)
        #pragma unroll
        for (int j=0;j<8;++j) acc2[o2][j]=0ull;

    for (int p=0;p<2;++p){
        const float* xin = (p ? x1 : x0) + (size_t)b*CIN*HW;
        const float* Wb  = g_WfT + (size_t)(p*BB+b)*(IKK*COUT) + octile*64;
        for (int icc=0; icc<16; ++icc){
            __syncthreads();
            // weights: 4608 elements, coalesced (oc contiguous)
            #pragma unroll
            for (int j=0;j<18;++j){
                int l = j*256 + tid;
                int oc = l & 63, r = l >> 6;            // r = ic*9+kk, 0..71
                int rr = r/9, kk = r - rr*9;
                sW[rr][kk][oc] = Wb[(icc*72 + r)*COUT + oc];
            }
            // input tile: 8 ic x 10 rows x 34 cols, zero-padded at borders
            #pragma unroll
            for (int j=0;j<11;++j){
                int l = j*256 + tid;
                if (l < 2720){
                    int col = l % 34; int rr = l / 34;
                    int row = rr % 10; int ic = rr / 10;
                    int gy = ybase - 1 + row, gx = xbase - 1 + col;
                    float v = 0.f;
                    if (gy >= 0 && gy < HH && gx >= 0 && gx < WW)
                        v = xin[(size_t)(icc*8+ic)*HW + gy*WW + gx];
                    sInp[ic][row][col] = v;
                }
            }
            __syncthreads();
            #pragma unroll 1
            for (int ic=0; ic<8; ++ic){
                #pragma unroll
                for (int ky=0; ky<3; ++ky){
                    unsigned long long rvd[10];
                    #pragma unroll
                    for (int j=0;j<10;++j){
                        float v = sInp[ic][qy+ky][qx*8 + j];
                        rvd[j] = pack2(v, v);
                    }
                    #pragma unroll
                    for (int kx=0; kx<3; ++kx){
                        unsigned long long wp[4];
                        #pragma unroll
                        for (int o2=0;o2<4;++o2)
                            wp[o2] = *(const unsigned long long*)&sW[ic][ky*3+kx][og*8 + o2*2];
                        #pragma unroll
                        for (int o2=0;o2<4;++o2)
                            #pragma unroll
                            for (int j=0;j<8;++j)
                                acc2[o2][j] = ffma2(wp[o2], rvd[kx+j], acc2[o2][j]);
                    }
                }
            }
        }
    }
    int yy = ybase + qy, xx = xbase + qx*8;
    #pragma unroll
    for (int o2=0;o2<4;++o2){
        int ocA = octile*64 + og*8 + o2*2;
        float bA = fuse_b[ocA], bB = fuse_b[ocA+1];
        float a[8], c[8];
        #pragma unroll
        for (int j=0;j<8;++j){
            float2 v = unpack2(acc2[o2][j]);
            a[j] = v.x + bA;
            c[j] = v.y + bB;
        }
        float* oA = &out[(((size_t)b*COUT + ocA  )*HH + yy)*WW + xx];
        float* oB = &out[(((size_t)b*COUT + ocA+1)*HH + yy)*WW + xx];
        *(float4*)&oA[0] = make_float4(a[0],a[1],a[2],a[3]);
        *(float4*)&oA[4] = make_float4(a[4],a[5],a[6],a[7]);
        *(float4*)&oB[0] = make_float4(c[0],c[1],c[2],c[3]);
        *(float4*)&oB[4] = make_float4(c[4],c[5],c[6],c[7]);
    }
}

// ---------------------------------------------------------------------------
// Launch
// ---------------------------------------------------------------------------
extern "C" void kernel_launch(void* const* d_in, const int* in_sizes, int n_in,
                              void* d_out, int out_size){
    const float* x0     = (const float*)d_in[0];
    const float* x1     = (const float*)d_in[1];
    const float* fc_w   = (const float*)d_in[2];
    const float* ln_g   = (const float*)d_in[3];
    const float* ln_b   = (const float*)d_in[4];
    const float* ch_w   = (const float*)d_in[5];
    const float* ch_b   = (const float*)d_in[6];
    const float* fl_w   = (const float*)d_in[7];
    const float* fl_b   = (const float*)d_in[8];
    const float* sp_w   = (const float*)d_in[9];
    const float* sp_b   = (const float*)d_in[10];
    const float* kn_w   = (const float*)d_in[11];
    const float* kn_b   = (const float*)d_in[12];
    const float* weight = (const float*)d_in[13];
    const float* mlp_w1 = (const float*)d_in[14];
    const float* mlp_b1 = (const float*)d_in[15];
    const float* mlp_w2 = (const float*)d_in[16];
    const float* mlp_b2 = (const float*)d_in[17];
    const float* fuse_w = (const float*)d_in[18];
    const float* fuse_b = (const float*)d_in[19];
    float* out = (float*)d_out;

    k_stats<<<BB*CIN, 256>>>(x0, x1);
    k_att<<<BB, 128>>>(fc_w, ln_g, ln_b, ch_w, ch_b, fl_w, fl_b,
                       sp_w, sp_b, kn_w, kn_b, mlp_w1, mlp_b1, mlp_w2, mlp_b2);
    k_agg<<<dim3(576, PB), 256>>>(weight);
    k_wf <<<dim3(18, PB), 256>>>(fuse_w);
    k_conv<<<dim3(100, 2, BB), 256>>>(x0, x1, fuse_b, out);
}

// round 7
// speedup vs baseline: 1.0012x; 1.0012x over previous
#include <cuda_runtime.h>
#include <math.h>

// ---------------------------------------------------------------------------
// Problem constants
// ---------------------------------------------------------------------------
#define BB    8
#define CIN   128
#define COUT  128
#define KK3   3
#define KN    4
#define HH    160
#define WW    160
#define ATT   16
#define MID   32
#define HW    (HH*WW)          // 25600
#define IKK   (CIN*9)          // 1152
#define PB    (2*BB)           // 16 (path, batch) combos

// ---------------------------------------------------------------------------
// Scratch (static device globals; no runtime allocation)
// ---------------------------------------------------------------------------
__device__ float g_gap0[BB*CIN];
__device__ float g_gap1[BB*CIN];
__device__ float g_fdmean[BB*CIN];
__device__ float g_fdmax[BB*CIN];

__device__ float g_ca[PB*CIN];     // [p*8+b][cin]   input-channel attention
__device__ float g_fa[PB*COUT];    // [pb][cout]     filter attention
__device__ float g_sM[PB*9];       // [pb][kk]       sa * Mfd
__device__ float g_ka[PB*KN];      // [pb][n]        kernel softmax

__device__ float g_A[PB*COUT*IKK];    // fa-folded, ka-mixed weights  [pb][c][ikk]
__device__ float g_WfT[PB*IKK*COUT];  // final folded weights         [pb][ikk][o]

__device__ __forceinline__ float sigm(float x){ return 1.f/(1.f+expf(-x)); }

// ---- packed f32x2 helpers (Blackwell FFMA2 path) --------------------------
__device__ __forceinline__ unsigned long long pack2(float lo, float hi){
    unsigned long long r;
    asm("mov.b64 %0, {%1, %2};" : "=l"(r) : "f"(lo), "f"(hi));
    return r;
}
__device__ __forceinline__ unsigned long long ffma2(unsigned long long a,
                                                    unsigned long long b,
                                                    unsigned long long c){
    unsigned long long d;
    asm("fma.rn.f32x2 %0, %1, %2, %3;" : "=l"(d) : "l"(a), "l"(b), "l"(c));
    return d;
}
__device__ __forceinline__ float2 unpack2(unsigned long long v){
    float lo, hi;
    asm("mov.b64 {%0, %1}, %2;" : "=f"(lo), "=f"(hi) : "l"(v));
    return make_float2(lo, hi);
}

// ---------------------------------------------------------------------------
// Kernel 1: per-(b,c) plane reductions: mean(x0), mean(x1), max(x0-x1)
// ---------------------------------------------------------------------------
__global__ __launch_bounds__(256) void k_stats(const float* __restrict__ x0,
                                               const float* __restrict__ x1){
    int bc = blockIdx.x;                         // 0..1023
    const float4* p0 = (const float4*)(x0 + (size_t)bc*HW);
    const float4* p1 = (const float4*)(x1 + (size_t)bc*HW);
    float s0=0.f, s1=0.f, mx=-3.0e38f;
    for (int i = threadIdx.x; i < HW/4; i += 256){
        float4 a = p0[i], b = p1[i];
        s0 += (a.x+a.y)+(a.z+a.w);
        s1 += (b.x+b.y)+(b.z+b.w);
        float d0 = a.x-b.x, d1 = a.y-b.y, d2 = a.z-b.z, d3 = a.w-b.w;
        mx = fmaxf(mx, fmaxf(fmaxf(d0,d1), fmaxf(d2,d3)));
    }
    #pragma unroll
    for (int off=16; off; off>>=1){
        s0 += __shfl_down_sync(0xffffffffu, s0, off);
        s1 += __shfl_down_sync(0xffffffffu, s1, off);
        mx  = fmaxf(mx, __shfl_down_sync(0xffffffffu, mx, off));
    }
    __shared__ float r0[8], r1[8], rm[8];
    int w = threadIdx.x >> 5;
    if ((threadIdx.x & 31) == 0){ r0[w]=s0; r1[w]=s1; rm[w]=mx; }
    __syncthreads();
    if (threadIdx.x == 0){
        float S0=0.f, S1=0.f, M=-3.0e38f;
        #pragma unroll
        for (int i=0;i<8;++i){ S0+=r0[i]; S1+=r1[i]; M=fmaxf(M, rm[i]); }
        const float inv = 1.f/(float)HW;
        g_gap0[bc]   = S0*inv;
        g_gap1[bc]   = S1*inv;
        g_fdmean[bc] = (S0-S1)*inv;
        g_fdmax[bc]  = M;
    }
}

// ---------------------------------------------------------------------------
// Kernel 2: attention + dif_atten (one block per batch, 128 threads)
// ---------------------------------------------------------------------------
__global__ __launch_bounds__(128) void k_att(
    const float* __restrict__ fc_w,  const float* __restrict__ ln_g,  const float* __restrict__ ln_b,
    const float* __restrict__ ch_w,  const float* __restrict__ ch_b,
    const float* __restrict__ fl_w,  const float* __restrict__ fl_b,
    const float* __restrict__ sp_w,  const float* __restrict__ sp_b,
    const float* __restrict__ kn_w,  const float* __restrict__ kn_b,
    const float* __restrict__ mlp_w1,const float* __restrict__ mlp_b1,
    const float* __restrict__ mlp_w2,const float* __restrict__ mlp_b2)
{
    int b = blockIdx.x, tid = threadIdx.x;
    __shared__ float gA[128], gB[128], yv[ATT], hs[MID], mfd[9], kl[KN];

    // ---- Mfd (shared across both paths) ----
    gA[tid] = g_fdmean[b*CIN + tid];
    gB[tid] = g_fdmax [b*CIN + tid];
    __syncthreads();
    if (tid < MID){
        float sa_ = mlp_b1[tid], sm_ = mlp_b1[tid];
        for (int c=0;c<CIN;++c){ float w = mlp_w1[tid*CIN+c]; sa_ += w*gA[c]; sm_ += w*gB[c]; }
        hs[tid] = fmaxf(sa_,0.f) + fmaxf(sm_,0.f);
    }
    __syncthreads();
    if (tid < 9){
        float z = 2.f*mlp_b2[tid];
        for (int t=0;t<MID;++t) z += mlp_w2[tid*MID+t]*hs[t];
        mfd[tid] = sigm(z);
    }

    // ---- attention per path ----
    for (int p=0;p<2;++p){
        __syncthreads();
        gA[tid] = (p ? g_gap1 : g_gap0)[b*CIN + tid];
        __syncthreads();
        if (tid < ATT){
            float v = 0.f;
            for (int c=0;c<CIN;++c) v += fc_w[tid*CIN+c]*gA[c];
            yv[tid] = v;
        }
        __syncthreads();
        if (tid == 0){
            float mu = 0.f;
            for (int j=0;j<ATT;++j) mu += yv[j];
            mu *= (1.f/ATT);
            float var = 0.f;
            for (int j=0;j<ATT;++j){ float d = yv[j]-mu; var += d*d; }
            var *= (1.f/ATT);
            float inv = rsqrtf(var + 1e-5f);
            for (int j=0;j<ATT;++j)
                yv[j] = fmaxf(0.f, (yv[j]-mu)*inv*ln_g[j] + ln_b[j]);
        }
        __syncthreads();
        {
            float ac = ch_b[tid], af = fl_b[tid];
            for (int j=0;j<ATT;++j){ ac += ch_w[tid*ATT+j]*yv[j]; af += fl_w[tid*ATT+j]*yv[j]; }
            g_ca[(p*BB+b)*CIN  + tid] = sigm(ac);
            g_fa[(p*BB+b)*COUT + tid] = sigm(af);
        }
        if (tid < 9){
            float s = sp_b[tid];
            for (int j=0;j<ATT;++j) s += sp_w[tid*ATT+j]*yv[j];
            g_sM[(p*BB+b)*9 + tid] = sigm(s)*mfd[tid];
        }
        if (tid < KN){
            float l = kn_b[tid];
            for (int j=0;j<ATT;++j) l += kn_w[tid*ATT+j]*yv[j];
            kl[tid] = l;
        }
        __syncthreads();
        if (tid == 0){
            float m = fmaxf(fmaxf(kl[0],kl[1]), fmaxf(kl[2],kl[3]));
            float e0=expf(kl[0]-m), e1=expf(kl[1]-m), e2=expf(kl[2]-m), e3=expf(kl[3]-m);
            float s = e0+e1+e2+e3;
            g_ka[(p*BB+b)*KN+0] = e0/s; g_ka[(p*BB+b)*KN+1] = e1/s;
            g_ka[(p*BB+b)*KN+2] = e2/s; g_ka[(p*BB+b)*KN+3] = e3/s;
        }
    }
}

// ---------------------------------------------------------------------------
// Kernel 3a: A[pb][c][ikk] = fa[pb][c] * sum_n ka[pb][n]*weight[n][c][ikk]
// ---------------------------------------------------------------------------
__global__ __launch_bounds__(256) void k_agg(const float* __restrict__ weight){
    int pb  = blockIdx.y;
    int idx = blockIdx.x*256 + threadIdx.x;   // < 128*1152 = 147456
    int c   = idx / IKK;
    float k0 = g_ka[pb*KN+0], k1 = g_ka[pb*KN+1], k2 = g_ka[pb*KN+2], k3 = g_ka[pb*KN+3];
    const float* w = weight + idx;            // weight[(n*128+c)*1152+ikk] = weight[n*147456 + idx]
    float acc = k0*w[0] + k1*w[COUT*IKK] + k2*w[2*COUT*IKK] + k3*w[3*COUT*IKK];
    g_A[pb*(COUT*IKK) + idx] = acc * g_fa[pb*COUT + c];
}

// ---------------------------------------------------------------------------
// Kernel 3b: WfT[pb][ikk][o] = ca[i]*sM[kk] * sum_c fuse_w[o, p*128+c]*A[pb][c][ikk]
//   GEMM M=128(o) x N=64(ikk tile) x K=128(c);  grid (18 ntiles, 16 pb)
// ---------------------------------------------------------------------------
__global__ __launch_bounds__(256) void k_wf(const float* __restrict__ fuse_w){
    int pb = blockIdx.y, p = pb >> 3;
    int nt = blockIdx.x;
    int tid = threadIdx.x;
    int to = tid & 15;        // o-group: o = to*8 .. to*8+7
    int tn = tid >> 4;        // ikk-group: nn = tn*4 .. tn*4+3
    __shared__ __align__(16) float Fs[16][128];
    __shared__ __align__(16) float As[16][64];
    float acc[8][4];
    #pragma unroll
    for (int o=0;o<8;++o)
        #pragma unroll
        for (int n=0;n<4;++n) acc[o][n]=0.f;

    const float* Abase = g_A + (size_t)pb*(COUT*IKK);
    for (int ck=0; ck<8; ++ck){
        __syncthreads();
        #pragma unroll
        for (int j=0;j<8;++j){          // 2048 fuse elements
            int l = j*256 + tid; int o = l & 127, cc = l >> 7;
            Fs[cc][o] = fuse_w[o*(2*COUT) + p*COUT + ck*16 + cc];
        }
        #pragma unroll
        for (int j=0;j<4;++j){          // 1024 A elements
            int l = j*256 + tid; int nn = l & 63, cc = l >> 6;
            As[cc][nn] = Abase[(ck*16+cc)*IKK + nt*64 + nn];
        }
        __syncthreads();
        #pragma unroll
        for (int cc=0; cc<16; ++cc){
            float4 av = *(const float4*)&As[cc][tn*4];
            float a_[4] = {av.x, av.y, av.z, av.w};
            float4 f0 = *(const float4*)&Fs[cc][to*8];
            float4 f1 = *(const float4*)&Fs[cc][to*8+4];
            float f_[8] = {f0.x,f0.y,f0.z,f0.w, f1.x,f1.y,f1.z,f1.w};
            #pragma unroll
            for (int o=0;o<8;++o)
                #pragma unroll
                for (int n=0;n<4;++n)
                    acc[o][n] = fmaf(f_[o], a_[n], acc[o][n]);
        }
    }
    float* Wbase = g_WfT + (size_t)pb*(IKK*COUT);
    const float* cap = g_ca + pb*CIN;
    const float* sMp = g_sM + pb*9;
    #pragma unroll
    for (int n=0;n<4;++n){
        int ikk = nt*64 + tn*4 + n;
        int i = ikk/9, kk = ikk - i*9;
        float sc = cap[i]*sMp[kk];
        #pragma unroll
        for (int o=0;o<8;++o)
            Wbase[ikk*COUT + to*8 + o] = acc[o][n]*sc;
    }
}

// ---------------------------------------------------------------------------
// Kernel 4: direct 3x3 conv via packed FFMA2, both paths summed, + fuse bias.
//   Block: 256 thr, tile = 64 out-ch x (8y x 32x), thread = 8 oc x 8 px.
//   oc handled as 4 packed pairs (f32x2 lanes). Grid: (100, 2, 8)
//   sInp row stride 35: compute-read bank = (3*qy + 8*qx) mod 32 -> conflict-free.
// ---------------------------------------------------------------------------
__global__ __launch_bounds__(256) void k_conv(const float* __restrict__ x0,
                                              const float* __restrict__ x1,
                                              const float* __restrict__ fuse_b,
                                              float* __restrict__ out){
    int b = blockIdx.z, octile = blockIdx.y;
    int tile = blockIdx.x;
    int txl = tile % 5, tyl = tile / 5;
    int xbase = txl*32, ybase = tyl*8;
    int tid = threadIdx.x;
    int q  = tid & 31, og = tid >> 5;
    int qy = q >> 2,  qx = q & 3;          // 8 rows x 4 col-groups (8 px each)

    __shared__ float sInp[8][10][35];              // 8 ic, 10 rows, 34 used cols (stride 35)
    __shared__ __align__(16) float sW[8][9][64];   // 8 ic, 9 taps, 64 oc

    unsigned long long acc2[4][8];                 // [oc-pair][pixel j]
    #pragma unroll
    for (int o2=0;o2<4;++o2)
        #pragma unroll
        for (int j=0;j<8;++j) acc2[o2][j]=0ull;

    for (int p=0;p<2;++p){
        const float* xin = (p ? x1 : x0) + (size_t)b*CIN*HW;
        const float* Wb  = g_WfT + (size_t)(p*BB+b)*(IKK*COUT) + octile*64;
        for (int icc=0; icc<16; ++icc){
            __syncthreads();
            // weights: 4608 elements, coalesced (oc contiguous)
            #pragma unroll
            for (int j=0;j<18;++j){
                int l = j*256 + tid;
                int oc = l & 63, r = l >> 6;            // r = ic*9+kk, 0..71
                int rr = r/9, kk = r - rr*9;
                sW[rr][kk][oc] = Wb[(icc*72 + r)*COUT + oc];
            }
            // input tile: 8 ic x 10 rows x 34 cols, zero-padded at borders
            #pragma unroll
            for (int j=0;j<11;++j){
                int l = j*256 + tid;
                if (l < 2720){
                    int col = l % 34; int rr = l / 34;
                    int row = rr % 10; int ic = rr / 10;
                    int gy = ybase - 1 + row, gx = xbase - 1 + col;
                    float v = 0.f;
                    if (gy >= 0 && gy < HH && gx >= 0 && gx < WW)
                        v = xin[(size_t)(icc*8+ic)*HW + gy*WW + gx];
                    sInp[ic][row][col] = v;
                }
            }
            __syncthreads();
            #pragma unroll 1
            for (int ic=0; ic<8; ++ic){
                #pragma unroll
                for (int ky=0; ky<3; ++ky){
                    unsigned long long rvd[10];
                    #pragma unroll
                    for (int j=0;j<10;++j){
                        float v = sInp[ic][qy+ky][qx*8 + j];
                        rvd[j] = pack2(v, v);
                    }
                    #pragma unroll
                    for (int kx=0; kx<3; ++kx){
                        unsigned long long wp[4];
                        #pragma unroll
                        for (int o2=0;o2<4;++o2)
                            wp[o2] = *(const unsigned long long*)&sW[ic][ky*3+kx][og*8 + o2*2];
                        #pragma unroll
                        for (int o2=0;o2<4;++o2)
                            #pragma unroll
                            for (int j=0;j<8;++j)
                                acc2[o2][j] = ffma2(wp[o2], rvd[kx+j], acc2[o2][j]);
                    }
                }
            }
        }
    }
    int yy = ybase + qy, xx = xbase + qx*8;
    #pragma unroll
    for (int o2=0;o2<4;++o2){
        int ocA = octile*64 + og*8 + o2*2;
        float bA = fuse_b[ocA], bB = fuse_b[ocA+1];
        float a[8], c[8];
        #pragma unroll
        for (int j=0;j<8;++j){
            float2 v = unpack2(acc2[o2][j]);
            a[j] = v.x + bA;
            c[j] = v.y + bB;
        }
        float* oA = &out[(((size_t)b*COUT + ocA  )*HH + yy)*WW + xx];
        float* oB = &out[(((size_t)b*COUT + ocA+1)*HH + yy)*WW + xx];
        *(float4*)&oA[0] = make_float4(a[0],a[1],a[2],a[3]);
        *(float4*)&oA[4] = make_float4(a[4],a[5],a[6],a[7]);
        *(float4*)&oB[0] = make_float4(c[0],c[1],c[2],c[3]);
        *(float4*)&oB[4] = make_float4(c[4],c[5],c[6],c[7]);
    }
}

// ---------------------------------------------------------------------------
// Launch
// ---------------------------------------------------------------------------
extern "C" void kernel_launch(void* const* d_in, const int* in_sizes, int n_in,
                              void* d_out, int out_size){
    const float* x0     = (const float*)d_in[0];
    const float* x1     = (const float*)d_in[1];
    const float* fc_w   = (const float*)d_in[2];
    const float* ln_g   = (const float*)d_in[3];
    const float* ln_b   = (const float*)d_in[4];
    const float* ch_w   = (const float*)d_in[5];
    const float* ch_b   = (const float*)d_in[6];
    const float* fl_w   = (const float*)d_in[7];
    const float* fl_b   = (const float*)d_in[8];
    const float* sp_w   = (const float*)d_in[9];
    const float* sp_b   = (const float*)d_in[10];
    const float* kn_w   = (const float*)d_in[11];
    const float* kn_b   = (const float*)d_in[12];
    const float* weight = (const float*)d_in[13];
    const float* mlp_w1 = (const float*)d_in[14];
    const float* mlp_b1 = (const float*)d_in[15];
    const float* mlp_w2 = (const float*)d_in[16];
    const float* mlp_b2 = (const float*)d_in[17];
    const float* fuse_w = (const float*)d_in[18];
    const float* fuse_b = (const float*)d_in[19];
    float* out = (float*)d_out;

    k_stats<<<BB*CIN, 256>>>(x0, x1);
    k_att<<<BB, 128>>>(fc_w, ln_g, ln_b, ch_w, ch_b, fl_w, fl_b,
                       sp_w, sp_b, kn_w, kn_b, mlp_w1, mlp_b1, mlp_w2, mlp_b2);
    k_agg<<<dim3(576, PB), 256>>>(weight);
    k_wf <<<dim3(18, PB), 256>>>(fuse_w);
    k_conv<<<dim3(100, 2, BB), 256>>>(x0, x1, fuse_b, out);
}

// round 9
// speedup vs baseline: 1.9381x; 1.9357x over previous
#include <cuda_runtime.h>
#include <math.h>

#define BB 8
#define CIN 128
#define COUT 128
#define KN 4
#define HH 160
#define WW 160
#define ATT 16
#define MID 32
#define HW (HH*WW)
#define IKK (CIN*9)
#define PB 16

#define NPX 256                 // pixels per CTA tile
#define NTHR 512
#define STG_WORDS 15360         // per stage: A 128*40 + B 256*40 floats
#define SMEM_BYTES (2*STG_WORDS*4)

__device__ float g_gap0[BB*CIN];
__device__ float g_gap1[BB*CIN];
__device__ float g_fdmean[BB*CIN];
__device__ float g_fdmax[BB*CIN];
__device__ float g_ca[PB*CIN];
__device__ float g_fa[PB*COUT];
__device__ float g_sM[PB*9];
__device__ float g_ka[PB*KN];
__device__ float g_A[PB*COUT*IKK];
__device__ float g_WfT[PB*IKK*COUT];            // tf32-rounded folded weights [ikk][oc]
__device__ __align__(16) float g_xT[(size_t)PB*HW*CIN];  // tf32-rounded NHWC inputs

__device__ __forceinline__ float sigm(float x){ return 1.f/(1.f+expf(-x)); }
__device__ __forceinline__ float to_tf32(float x){
    float r; asm("cvt.rna.tf32.f32 %0, %1;" : "=f"(r) : "f"(x)); return r;
}
__device__ __forceinline__ void mma_tf32(float* c, const unsigned* a, const unsigned* b){
    asm volatile(
        "mma.sync.aligned.m16n8k8.row.col.f32.tf32.tf32.f32 "
        "{%0,%1,%2,%3}, {%4,%5,%6,%7}, {%8,%9}, {%0,%1,%2,%3};"
        : "+f"(c[0]), "+f"(c[1]), "+f"(c[2]), "+f"(c[3])
        : "r"(a[0]), "r"(a[1]), "r"(a[2]), "r"(a[3]), "r"(b[0]), "r"(b[1]));
}

// ---------------- k_stats ----------------
__global__ __launch_bounds__(256) void k_stats(const float* __restrict__ x0,
                                               const float* __restrict__ x1){
    int bc = blockIdx.x;
    const float4* p0 = (const float4*)(x0 + (size_t)bc*HW);
    const float4* p1 = (const float4*)(x1 + (size_t)bc*HW);
    float s0=0.f, s1=0.f, mx=-3.0e38f;
    for (int i = threadIdx.x; i < HW/4; i += 256){
        float4 a = p0[i], b = p1[i];
        s0 += (a.x+a.y)+(a.z+a.w);
        s1 += (b.x+b.y)+(b.z+b.w);
        mx = fmaxf(mx, fmaxf(fmaxf(a.x-b.x,a.y-b.y), fmaxf(a.z-b.z,a.w-b.w)));
    }
    #pragma unroll
    for (int off=16; off; off>>=1){
        s0 += __shfl_down_sync(0xffffffffu, s0, off);
        s1 += __shfl_down_sync(0xffffffffu, s1, off);
        mx  = fmaxf(mx, __shfl_down_sync(0xffffffffu, mx, off));
    }
    __shared__ float r0[8], r1[8], rm[8];
    int w = threadIdx.x >> 5;
    if ((threadIdx.x & 31) == 0){ r0[w]=s0; r1[w]=s1; rm[w]=mx; }
    __syncthreads();
    if (threadIdx.x == 0){
        float S0=0.f, S1=0.f, M=-3.0e38f;
        #pragma unroll
        for (int i=0;i<8;++i){ S0+=r0[i]; S1+=r1[i]; M=fmaxf(M, rm[i]); }
        const float inv = 1.f/(float)HW;
        g_gap0[bc]=S0*inv; g_gap1[bc]=S1*inv; g_fdmean[bc]=(S0-S1)*inv; g_fdmax[bc]=M;
    }
}

// ---------------- k_att ----------------
__global__ __launch_bounds__(128) void k_att(
    const float* __restrict__ fc_w,  const float* __restrict__ ln_g,  const float* __restrict__ ln_b,
    const float* __restrict__ ch_w,  const float* __restrict__ ch_b,
    const float* __restrict__ fl_w,  const float* __restrict__ fl_b,
    const float* __restrict__ sp_w,  const float* __restrict__ sp_b,
    const float* __restrict__ kn_w,  const float* __restrict__ kn_b,
    const float* __restrict__ mlp_w1,const float* __restrict__ mlp_b1,
    const float* __restrict__ mlp_w2,const float* __restrict__ mlp_b2)
{
    int b = blockIdx.x, tid = threadIdx.x;
    __shared__ float gA[128], gB[128], yv[ATT], hs[MID], mfd[9], kl[KN];
    gA[tid] = g_fdmean[b*CIN + tid];
    gB[tid] = g_fdmax [b*CIN + tid];
    __syncthreads();
    if (tid < MID){
        float sa_ = mlp_b1[tid], sm_ = mlp_b1[tid];
        for (int c=0;c<CIN;++c){ float w = mlp_w1[tid*CIN+c]; sa_ += w*gA[c]; sm_ += w*gB[c]; }
        hs[tid] = fmaxf(sa_,0.f) + fmaxf(sm_,0.f);
    }
    __syncthreads();
    if (tid < 9){
        float z = 2.f*mlp_b2[tid];
        for (int t=0;t<MID;++t) z += mlp_w2[tid*MID+t]*hs[t];
        mfd[tid] = sigm(z);
    }
    for (int p=0;p<2;++p){
        __syncthreads();
        gA[tid] = (p ? g_gap1 : g_gap0)[b*CIN + tid];
        __syncthreads();
        if (tid < ATT){
            float v = 0.f;
            for (int c=0;c<CIN;++c) v += fc_w[tid*CIN+c]*gA[c];
            yv[tid] = v;
        }
        __syncthreads();
        if (tid == 0){
            float mu = 0.f;
            for (int j=0;j<ATT;++j) mu += yv[j];
            mu *= (1.f/ATT);
            float var = 0.f;
            for (int j=0;j<ATT;++j){ float d = yv[j]-mu; var += d*d; }
            var *= (1.f/ATT);
            float inv = rsqrtf(var + 1e-5f);
            for (int j=0;j<ATT;++j)
                yv[j] = fmaxf(0.f, (yv[j]-mu)*inv*ln_g[j] + ln_b[j]);
        }
        __syncthreads();
        {
            float ac = ch_b[tid], af = fl_b[tid];
            for (int j=0;j<ATT;++j){ ac += ch_w[tid*ATT+j]*yv[j]; af += fl_w[tid*ATT+j]*yv[j]; }
            g_ca[(p*BB+b)*CIN  + tid] = sigm(ac);
            g_fa[(p*BB+b)*COUT + tid] = sigm(af);
        }
        if (tid < 9){
            float s = sp_b[tid];
            for (int j=0;j<ATT;++j) s += sp_w[tid*ATT+j]*yv[j];
            g_sM[(p*BB+b)*9 + tid] = sigm(s)*mfd[tid];
        }
        if (tid < KN){
            float l = kn_b[tid];
            for (int j=0;j<ATT;++j) l += kn_w[tid*ATT+j]*yv[j];
            kl[tid] = l;
        }
        __syncthreads();
        if (tid == 0){
            float m = fmaxf(fmaxf(kl[0],kl[1]), fmaxf(kl[2],kl[3]));
            float e0=expf(kl[0]-m), e1=expf(kl[1]-m), e2=expf(kl[2]-m), e3=expf(kl[3]-m);
            float s = e0+e1+e2+e3;
            g_ka[(p*BB+b)*KN+0]=e0/s; g_ka[(p*BB+b)*KN+1]=e1/s;
            g_ka[(p*BB+b)*KN+2]=e2/s; g_ka[(p*BB+b)*KN+3]=e3/s;
        }
    }
}

// ---------------- k_agg ----------------
__global__ __launch_bounds__(256) void k_agg(const float* __restrict__ weight){
    int pb  = blockIdx.y;
    int idx = blockIdx.x*256 + threadIdx.x;
    int c   = idx / IKK;
    float k0=g_ka[pb*KN+0], k1=g_ka[pb*KN+1], k2=g_ka[pb*KN+2], k3=g_ka[pb*KN+3];
    const float* w = weight + idx;
    float acc = k0*w[0] + k1*w[COUT*IKK] + k2*w[2*COUT*IKK] + k3*w[3*COUT*IKK];
    g_A[pb*(COUT*IKK) + idx] = acc * g_fa[pb*COUT + c];
}

// ---------------- k_wf : fuse-GEMM + scales -> tf32-rounded [ikk][oc] ----------
__global__ __launch_bounds__(256) void k_wf(const float* __restrict__ fuse_w){
    int pb = blockIdx.y, p = pb >> 3;
    int nt = blockIdx.x;
    int tid = threadIdx.x;
    int to = tid & 15, tn = tid >> 4;
    __shared__ __align__(16) float Fs[16][128];
    __shared__ __align__(16) float As[16][64];
    float acc[8][4];
    #pragma unroll
    for (int o=0;o<8;++o)
        #pragma unroll
        for (int n=0;n<4;++n) acc[o][n]=0.f;
    const float* Abase = g_A + (size_t)pb*(COUT*IKK);
    for (int ck=0; ck<8; ++ck){
        __syncthreads();
        #pragma unroll
        for (int j=0;j<8;++j){
            int l = j*256 + tid; int o = l & 127, cc = l >> 7;
            Fs[cc][o] = fuse_w[o*(2*COUT) + p*COUT + ck*16 + cc];
        }
        #pragma unroll
        for (int j=0;j<4;++j){
            int l = j*256 + tid; int nn = l & 63, cc = l >> 6;
            As[cc][nn] = Abase[(ck*16+cc)*IKK + nt*64 + nn];
        }
        __syncthreads();
        #pragma unroll
        for (int cc=0; cc<16; ++cc){
            float4 av = *(const float4*)&As[cc][tn*4];
            float a_[4] = {av.x, av.y, av.z, av.w};
            float4 f0 = *(const float4*)&Fs[cc][to*8];
            float4 f1 = *(const float4*)&Fs[cc][to*8+4];
            float f_[8] = {f0.x,f0.y,f0.z,f0.w, f1.x,f1.y,f1.z,f1.w};
            #pragma unroll
            for (int o=0;o<8;++o)
                #pragma unroll
                for (int n=0;n<4;++n)
                    acc[o][n] = fmaf(f_[o], a_[n], acc[o][n]);
        }
    }
    float* Wbase = g_WfT + (size_t)pb*(IKK*COUT);
    const float* cap = g_ca + pb*CIN;
    const float* sMp = g_sM + pb*9;
    #pragma unroll
    for (int n=0;n<4;++n){
        int ikk = nt*64 + tn*4 + n;
        int i = ikk/9, kk = ikk - i*9;
        float sc = cap[i]*sMp[kk];
        #pragma unroll
        for (int o=0;o<8;++o)
            Wbase[ikk*COUT + to*8 + o] = to_tf32(acc[o][n]*sc);
    }
}

// ---------------- k_tr : NCHW fp32 -> NHWC tf32-rounded fp32 ----------------
__global__ __launch_bounds__(256) void k_tr(const float* __restrict__ x0,
                                            const float* __restrict__ x1){
    int px0 = blockIdx.x*128, ic0 = blockIdx.y*32, z = blockIdx.z;
    const float* src = (z >= 8 ? x1 : x0) + ((size_t)(z&7)*CIN + ic0)*HW + px0;
    __shared__ float t[32][129];
    int tid = threadIdx.x, lane = tid & 31, w = tid >> 5;
    #pragma unroll
    for (int i=0;i<4;++i){
        int ic = w + i*8;
        float4 v = *(const float4*)(src + (size_t)ic*HW + lane*4);
        t[ic][lane*4+0]=v.x; t[ic][lane*4+1]=v.y; t[ic][lane*4+2]=v.z; t[ic][lane*4+3]=v.w;
    }
    __syncthreads();
    int px = tid >> 1, icg = (tid & 1)*16;
    float* dst = g_xT + ((size_t)z*HW + px0 + px)*CIN + ic0 + icg;
    #pragma unroll
    for (int j=0;j<4;++j){
        float4 v;
        v.x = to_tf32(t[icg+4*j+0][px]);
        v.y = to_tf32(t[icg+4*j+1][px]);
        v.z = to_tf32(t[icg+4*j+2][px]);
        v.w = to_tf32(t[icg+4*j+3][px]);
        *(float4*)(dst + 4*j) = v;
    }
}

// ---------------- k_conv : tf32 mma.sync implicit conv ----------------
// CTA: D[128 oc][256 px], K = 72 chunks of 32 (path,tap,ic-quarter).
// smem per stage: sA[128 oc][40] (k pair-interleaved), sB[256 px][40].
__global__ __launch_bounds__(NTHR) void k_conv(const float* __restrict__ fuse_b,
                                               float* __restrict__ out){
    extern __shared__ float dsm[];
    __shared__ float sBias[128];
    int b = blockIdx.y;
    int px0 = blockIdx.x*NPX;
    int tid = threadIdx.x;
    int lane = tid & 31, wid = tid >> 5;
    int wm = wid >> 3, wn = wid & 7;     // warp tile: 64 oc x 32 px
    int g = lane >> 2, tg = lane & 3;
    if (tid < 128) sBias[tid] = fuse_b[tid];

    float acc[4][4][4];
    #pragma unroll
    for (int mt=0;mt<4;++mt)
        #pragma unroll
        for (int nt=0;nt<4;++nt)
            #pragma unroll
            for (int e=0;e<4;++e) acc[mt][nt][e]=0.f;

    // ---- staging lambda (chunk c into stage s) ----
    auto stage = [&](int c, int s){
        int p = c / 36, r = c - p*36;
        int tap = r >> 2, icq = r & 3;
        int ic0 = icq*32;
        int dy = tap/3, dx = tap - dy*3;
        int pb = p*BB + b;
        float* sA = dsm + s*STG_WORDS;
        float* sB = sA + 128*40;
        // A: 128 oc x 32 kk from g_WfT[(ic0+kk)*9+tap][oc]
        const float* Wb = g_WfT + (size_t)pb*(IKK*COUT);
        #pragma unroll
        for (int j=0;j<8;++j){
            int l = j*NTHR + tid;
            int oc = l & 127, kk = l >> 7;
            int slot = ((kk>>3)<<3) + ((kk&3)<<1) + ((kk>>2)&1);
            sA[oc*40 + slot] = Wb[((ic0+kk)*9+tap)*COUT + oc];
        }
        // B: 256 px x 32 kk from g_xT (NHWC), with 3x3 halo masking
        {
            int px = tid >> 1, kh = (tid & 1) << 4;
            int pg = px0 + px;
            int y = pg / WW, x = pg - y*WW;
            int iy = y + dy - 1, ix = x + dx - 1;
            bool ok = ((unsigned)iy < (unsigned)HH) && ((unsigned)ix < (unsigned)WW);
            const float4* src = (const float4*)(g_xT + ((size_t)pb*HW + (size_t)iy*WW + ix)*CIN + ic0 + kh);
            #pragma unroll
            for (int j=0;j<4;++j){
                float4 v = ok ? src[j] : make_float4(0.f,0.f,0.f,0.f);
                float vv[4] = {v.x, v.y, v.z, v.w};
                #pragma unroll
                for (int e=0;e<4;++e){
                    int kk = kh + 4*j + e;
                    int slot = ((kk>>3)<<3) + ((kk&3)<<1) + ((kk>>2)&1);
                    sB[px*40 + slot] = vv[e];
                }
            }
        }
    };

    stage(0, 0);
    for (int c=0; c<72; ++c){
        __syncthreads();
        if (c+1 < 72) stage(c+1, (c+1)&1);
        // compute chunk c
        const float* sA = dsm + (c&1)*STG_WORDS;
        const float* sB = sA + 128*40;
        const float* Ab = sA + (wm*64 + g)*40;
        const float* Bb = sB + (wn*32 + g)*40;
        #pragma unroll
        for (int ks=0; ks<4; ++ks){
            int ko = ks*8 + 2*tg;
            unsigned af[4][4], bf[4][2];
            #pragma unroll
            for (int mt=0;mt<4;++mt){
                float2 x0 = *(const float2*)(Ab + mt*16*40 + ko);
                float2 x1 = *(const float2*)(Ab + mt*16*40 + 8*40 + ko);
                af[mt][0] = __float_as_uint(x0.x);   // (m, k)
                af[mt][1] = __float_as_uint(x1.x);   // (m+8, k)
                af[mt][2] = __float_as_uint(x0.y);   // (m, k+4)
                af[mt][3] = __float_as_uint(x1.y);   // (m+8, k+4)
            }
            #pragma unroll
            for (int nt=0;nt<4;++nt){
                float2 bv = *(const float2*)(Bb + nt*8*40 + ko);
                bf[nt][0] = __float_as_uint(bv.x);   // (k, n)
                bf[nt][1] = __float_as_uint(bv.y);   // (k+4, n)
            }
            #pragma unroll
            for (int mt=0;mt<4;++mt)
                #pragma unroll
                for (int nt=0;nt<4;++nt)
                    mma_tf32(acc[mt][nt], af[mt], bf[nt]);
        }
    }

    // epilogue: c0/c1 at (oc, n..n+1), c2/c3 at (oc+8, n..n+1)
    #pragma unroll
    for (int mt=0;mt<4;++mt){
        int oc = wm*64 + mt*16 + g;
        float b0 = sBias[oc], b1 = sBias[oc+8];
        #pragma unroll
        for (int nt=0;nt<4;++nt){
            int n = wn*32 + nt*8 + 2*tg;
            float* o0 = out + ((size_t)b*COUT + oc)*HW + px0 + n;
            float* o1 = out + ((size_t)b*COUT + oc + 8)*HW + px0 + n;
            *(float2*)o0 = make_float2(acc[mt][nt][0]+b0, acc[mt][nt][1]+b0);
            *(float2*)o1 = make_float2(acc[mt][nt][2]+b1, acc[mt][nt][3]+b1);
        }
    }
}

// ---------------- launch ----------------
extern "C" void kernel_launch(void* const* d_in, const int* in_sizes, int n_in,
                              void* d_out, int out_size){
    const float* x0     = (const float*)d_in[0];
    const float* x1     = (const float*)d_in[1];
    const float* fc_w   = (const float*)d_in[2];
    const float* ln_g   = (const float*)d_in[3];
    const float* ln_b   = (const float*)d_in[4];
    const float* ch_w   = (const float*)d_in[5];
    const float* ch_b   = (const float*)d_in[6];
    const float* fl_w   = (const float*)d_in[7];
    const float* fl_b   = (const float*)d_in[8];
    const float* sp_w   = (const float*)d_in[9];
    const float* sp_b   = (const float*)d_in[10];
    const float* kn_w   = (const float*)d_in[11];
    const float* kn_b   = (const float*)d_in[12];
    const float* weight = (const float*)d_in[13];
    const float* mlp_w1 = (const float*)d_in[14];
    const float* mlp_b1 = (const float*)d_in[15];
    const float* mlp_w2 = (const float*)d_in[16];
    const float* mlp_b2 = (const float*)d_in[17];
    const float* fuse_w = (const float*)d_in[18];
    const float* fuse_b = (const float*)d_in[19];
    float* out = (float*)d_out;

    cudaFuncSetAttribute(k_conv, cudaFuncAttributeMaxDynamicSharedMemorySize, SMEM_BYTES);

    k_stats<<<BB*CIN, 256>>>(x0, x1);
    k_att<<<BB, 128>>>(fc_w, ln_g, ln_b, ch_w, ch_b, fl_w, fl_b,
                       sp_w, sp_b, kn_w, kn_b, mlp_w1, mlp_b1, mlp_w2, mlp_b2);
    k_agg<<<dim3(576, PB), 256>>>(weight);
    k_wf <<<dim3(18, PB), 256>>>(fuse_w);
    k_tr <<<dim3(HW/128, CIN/32, PB), 256>>>(x0, x1);
    k_conv<<<dim3(HW/NPX, BB), NTHR, SMEM_BYTES>>>(fuse_b, out);
}

// round 10
// speedup vs baseline: 3.3101x; 1.7079x over previous
#include <cuda_runtime.h>
#include <math.h>

#define BB 8
#define CIN 128
#define COUT 128
#define KN 4
#define HH 160
#define WW 160
#define ATT 16
#define MID 32
#define HW (HH*WW)
#define IKK (CIN*9)
#define PB 16

#define NPX 256
#define NTHR 512
#define STG_BYTES 49152        // per stage: A 16KB + B 32KB
#define SMEM_BYTES (3*STG_BYTES)

__device__ float g_gap0[BB*CIN];
__device__ float g_gap1[BB*CIN];
__device__ float g_fdmean[BB*CIN];
__device__ float g_fdmax[BB*CIN];
__device__ float g_ca[PB*CIN];
__device__ float g_fa[PB*COUT];
__device__ float g_sM[PB*9];
__device__ float g_ka[PB*KN];
__device__ float g_A[PB*COUT*IKK];
// tf32-rounded folded weights, layout [pb][tap][oc][ic]
__device__ __align__(16) float g_WfT[(size_t)PB*9*COUT*CIN];
__device__ __align__(16) float g_xT[(size_t)PB*HW*CIN];  // tf32-rounded NHWC

__device__ __forceinline__ float sigm(float x){ return 1.f/(1.f+expf(-x)); }
__device__ __forceinline__ float to_tf32(float x){
    float r; asm("cvt.rna.tf32.f32 %0, %1;" : "=f"(r) : "f"(x)); return r;
}
__device__ __forceinline__ unsigned smem_u32(const void* p){
    unsigned a;
    asm("{ .reg .u64 t; cvta.to.shared.u64 t, %1; cvt.u32.u64 %0, t; }" : "=r"(a) : "l"(p));
    return a;
}
__device__ __forceinline__ void mma_tf32(float* c, const unsigned* a, const unsigned* b){
    asm volatile(
        "mma.sync.aligned.m16n8k8.row.col.f32.tf32.tf32.f32 "
        "{%0,%1,%2,%3}, {%4,%5,%6,%7}, {%8,%9}, {%0,%1,%2,%3};"
        : "+f"(c[0]), "+f"(c[1]), "+f"(c[2]), "+f"(c[3])
        : "r"(a[0]), "r"(a[1]), "r"(a[2]), "r"(a[3]), "r"(b[0]), "r"(b[1]));
}
__device__ __forceinline__ void ldsm4(unsigned* d, unsigned addr){
    asm volatile("ldmatrix.sync.aligned.m8n8.x4.shared.b16 {%0,%1,%2,%3}, [%4];"
        : "=r"(d[0]),"=r"(d[1]),"=r"(d[2]),"=r"(d[3]) : "r"(addr));
}
__device__ __forceinline__ void cp16(unsigned dst, const void* src, unsigned sz){
    asm volatile("cp.async.ca.shared.global [%0], [%1], 16, %2;"
        :: "r"(dst), "l"(src), "r"(sz) : "memory");
}

// ---------------- k_stats ----------------
__global__ __launch_bounds__(256) void k_stats(const float* __restrict__ x0,
                                               const float* __restrict__ x1){
    int bc = blockIdx.x;
    const float4* p0 = (const float4*)(x0 + (size_t)bc*HW);
    const float4* p1 = (const float4*)(x1 + (size_t)bc*HW);
    float s0=0.f, s1=0.f, mx=-3.0e38f;
    for (int i = threadIdx.x; i < HW/4; i += 256){
        float4 a = p0[i], b = p1[i];
        s0 += (a.x+a.y)+(a.z+a.w);
        s1 += (b.x+b.y)+(b.z+b.w);
        mx = fmaxf(mx, fmaxf(fmaxf(a.x-b.x,a.y-b.y), fmaxf(a.z-b.z,a.w-b.w)));
    }
    #pragma unroll
    for (int off=16; off; off>>=1){
        s0 += __shfl_down_sync(0xffffffffu, s0, off);
        s1 += __shfl_down_sync(0xffffffffu, s1, off);
        mx  = fmaxf(mx, __shfl_down_sync(0xffffffffu, mx, off));
    }
    __shared__ float r0[8], r1[8], rm[8];
    int w = threadIdx.x >> 5;
    if ((threadIdx.x & 31) == 0){ r0[w]=s0; r1[w]=s1; rm[w]=mx; }
    __syncthreads();
    if (threadIdx.x == 0){
        float S0=0.f, S1=0.f, M=-3.0e38f;
        #pragma unroll
        for (int i=0;i<8;++i){ S0+=r0[i]; S1+=r1[i]; M=fmaxf(M, rm[i]); }
        const float inv = 1.f/(float)HW;
        g_gap0[bc]=S0*inv; g_gap1[bc]=S1*inv; g_fdmean[bc]=(S0-S1)*inv; g_fdmax[bc]=M;
    }
}

// ---------------- k_att ----------------
__global__ __launch_bounds__(128) void k_att(
    const float* __restrict__ fc_w,  const float* __restrict__ ln_g,  const float* __restrict__ ln_b,
    const float* __restrict__ ch_w,  const float* __restrict__ ch_b,
    const float* __restrict__ fl_w,  const float* __restrict__ fl_b,
    const float* __restrict__ sp_w,  const float* __restrict__ sp_b,
    const float* __restrict__ kn_w,  const float* __restrict__ kn_b,
    const float* __restrict__ mlp_w1,const float* __restrict__ mlp_b1,
    const float* __restrict__ mlp_w2,const float* __restrict__ mlp_b2)
{
    int b = blockIdx.x, tid = threadIdx.x;
    __shared__ float gA[128], gB[128], yv[ATT], hs[MID], mfd[9], kl[KN];
    gA[tid] = g_fdmean[b*CIN + tid];
    gB[tid] = g_fdmax [b*CIN + tid];
    __syncthreads();
    if (tid < MID){
        float sa_ = mlp_b1[tid], sm_ = mlp_b1[tid];
        for (int c=0;c<CIN;++c){ float w = mlp_w1[tid*CIN+c]; sa_ += w*gA[c]; sm_ += w*gB[c]; }
        hs[tid] = fmaxf(sa_,0.f) + fmaxf(sm_,0.f);
    }
    __syncthreads();
    if (tid < 9){
        float z = 2.f*mlp_b2[tid];
        for (int t=0;t<MID;++t) z += mlp_w2[tid*MID+t]*hs[t];
        mfd[tid] = sigm(z);
    }
    for (int p=0;p<2;++p){
        __syncthreads();
        gA[tid] = (p ? g_gap1 : g_gap0)[b*CIN + tid];
        __syncthreads();
        if (tid < ATT){
            float v = 0.f;
            for (int c=0;c<CIN;++c) v += fc_w[tid*CIN+c]*gA[c];
            yv[tid] = v;
        }
        __syncthreads();
        if (tid == 0){
            float mu = 0.f;
            for (int j=0;j<ATT;++j) mu += yv[j];
            mu *= (1.f/ATT);
            float var = 0.f;
            for (int j=0;j<ATT;++j){ float d = yv[j]-mu; var += d*d; }
            var *= (1.f/ATT);
            float inv = rsqrtf(var + 1e-5f);
            for (int j=0;j<ATT;++j)
                yv[j] = fmaxf(0.f, (yv[j]-mu)*inv*ln_g[j] + ln_b[j]);
        }
        __syncthreads();
        {
            float ac = ch_b[tid], af = fl_b[tid];
            for (int j=0;j<ATT;++j){ ac += ch_w[tid*ATT+j]*yv[j]; af += fl_w[tid*ATT+j]*yv[j]; }
            g_ca[(p*BB+b)*CIN  + tid] = sigm(ac);
            g_fa[(p*BB+b)*COUT + tid] = sigm(af);
        }
        if (tid < 9){
            float s = sp_b[tid];
            for (int j=0;j<ATT;++j) s += sp_w[tid*ATT+j]*yv[j];
            g_sM[(p*BB+b)*9 + tid] = sigm(s)*mfd[tid];
        }
        if (tid < KN){
            float l = kn_b[tid];
            for (int j=0;j<ATT;++j) l += kn_w[tid*ATT+j]*yv[j];
            kl[tid] = l;
        }
        __syncthreads();
        if (tid == 0){
            float m = fmaxf(fmaxf(kl[0],kl[1]), fmaxf(kl[2],kl[3]));
            float e0=expf(kl[0]-m), e1=expf(kl[1]-m), e2=expf(kl[2]-m), e3=expf(kl[3]-m);
            float s = e0+e1+e2+e3;
            g_ka[(p*BB+b)*KN+0]=e0/s; g_ka[(p*BB+b)*KN+1]=e1/s;
            g_ka[(p*BB+b)*KN+2]=e2/s; g_ka[(p*BB+b)*KN+3]=e3/s;
        }
    }
}

// ---------------- k_agg ----------------
__global__ __launch_bounds__(256) void k_agg(const float* __restrict__ weight){
    int pb  = blockIdx.y;
    int idx = blockIdx.x*256 + threadIdx.x;
    int c   = idx / IKK;
    float k0=g_ka[pb*KN+0], k1=g_ka[pb*KN+1], k2=g_ka[pb*KN+2], k3=g_ka[pb*KN+3];
    const float* w = weight + idx;
    float acc = k0*w[0] + k1*w[COUT*IKK] + k2*w[2*COUT*IKK] + k3*w[3*COUT*IKK];
    g_A[pb*(COUT*IKK) + idx] = acc * g_fa[pb*COUT + c];
}

// ---------------- k_wf : fuse-GEMM + scales -> tf32 [tap][oc][ic] ----------
__global__ __launch_bounds__(256) void k_wf(const float* __restrict__ fuse_w){
    int pb = blockIdx.y, p = pb >> 3;
    int nt = blockIdx.x;
    int tid = threadIdx.x;
    int to = tid & 15, tn = tid >> 4;
    __shared__ __align__(16) float Fs[16][128];
    __shared__ __align__(16) float As[16][64];
    float acc[8][4];
    #pragma unroll
    for (int o=0;o<8;++o)
        #pragma unroll
        for (int n=0;n<4;++n) acc[o][n]=0.f;
    const float* Abase = g_A + (size_t)pb*(COUT*IKK);
    for (int ck=0; ck<8; ++ck){
        __syncthreads();
        #pragma unroll
        for (int j=0;j<8;++j){
            int l = j*256 + tid; int o = l & 127, cc = l >> 7;
            Fs[cc][o] = fuse_w[o*(2*COUT) + p*COUT + ck*16 + cc];
        }
        #pragma unroll
        for (int j=0;j<4;++j){
            int l = j*256 + tid; int nn = l & 63, cc = l >> 6;
            As[cc][nn] = Abase[(ck*16+cc)*IKK + nt*64 + nn];
        }
        __syncthreads();
        #pragma unroll
        for (int cc=0; cc<16; ++cc){
            float4 av = *(const float4*)&As[cc][tn*4];
            float a_[4] = {av.x, av.y, av.z, av.w};
            float4 f0 = *(const float4*)&Fs[cc][to*8];
            float4 f1 = *(const float4*)&Fs[cc][to*8+4];
            float f_[8] = {f0.x,f0.y,f0.z,f0.w, f1.x,f1.y,f1.z,f1.w};
            #pragma unroll
            for (int o=0;o<8;++o)
                #pragma unroll
                for (int n=0;n<4;++n)
                    acc[o][n] = fmaf(f_[o], a_[n], acc[o][n]);
        }
    }
    float* Wbase = g_WfT + (size_t)pb*9*COUT*CIN;
    const float* cap = g_ca + pb*CIN;
    const float* sMp = g_sM + pb*9;
    #pragma unroll
    for (int n=0;n<4;++n){
        int ikk = nt*64 + tn*4 + n;
        int ic = ikk/9, tap = ikk - ic*9;
        float sc = cap[ic]*sMp[tap];
        #pragma unroll
        for (int o=0;o<8;++o){
            int oc = to*8 + o;
            Wbase[((size_t)tap*COUT + oc)*CIN + ic] = to_tf32(acc[o][n]*sc);
        }
    }
}

// ---------------- k_tr : NCHW fp32 -> NHWC tf32-rounded ----------------
__global__ __launch_bounds__(256) void k_tr(const float* __restrict__ x0,
                                            const float* __restrict__ x1){
    int px0 = blockIdx.x*128, ic0 = blockIdx.y*32, z = blockIdx.z;
    const float* src = (z >= 8 ? x1 : x0) + ((size_t)(z&7)*CIN + ic0)*HW + px0;
    __shared__ float t[32][129];
    int tid = threadIdx.x, lane = tid & 31, w = tid >> 5;
    #pragma unroll
    for (int i=0;i<4;++i){
        int ic = w + i*8;
        float4 v = *(const float4*)(src + (size_t)ic*HW + lane*4);
        t[ic][lane*4+0]=v.x; t[ic][lane*4+1]=v.y; t[ic][lane*4+2]=v.z; t[ic][lane*4+3]=v.w;
    }
    __syncthreads();
    int px = tid >> 1, icg = (tid & 1)*16;
    float* dst = g_xT + ((size_t)z*HW + px0 + px)*CIN + ic0 + icg;
    #pragma unroll
    for (int j=0;j<4;++j){
        float4 v;
        v.x = to_tf32(t[icg+4*j+0][px]);
        v.y = to_tf32(t[icg+4*j+1][px]);
        v.z = to_tf32(t[icg+4*j+2][px]);
        v.w = to_tf32(t[icg+4*j+3][px]);
        *(float4*)(dst + 4*j) = v;
    }
}

// ---------------- k_conv : tf32 mma.sync + cp.async 3-stage + ldmatrix ------
// CTA: D[128 oc][256 px]; K = 72 chunks (path,tap,ic-quarter) of 32.
// Stage: sA[128 oc][32k] (+XOR swizzle), sB[256 px][32k] (+XOR swizzle).
__global__ __launch_bounds__(NTHR) void k_conv(const float* __restrict__ fuse_b,
                                               float* __restrict__ out){
    extern __shared__ float dsm[];
    __shared__ float sBias[128];
    int b = blockIdx.y;
    int px0 = blockIdx.x*NPX;
    int tid = threadIdx.x;
    int lane = tid & 31, wid = tid >> 5;
    int wm = wid >> 3, wn = wid & 7;     // warp: 64 oc x 32 px
    int g = lane >> 2, tg = lane & 3;
    int sel = lane >> 3, r8 = lane & 7;
    int rowA = r8 + ((sel & 1) << 3), kselA = sel >> 1;
    int rowB = r8 + ((sel >> 1) << 3), kselB = sel & 1;
    if (tid < 128) sBias[tid] = fuse_b[tid];
    unsigned smem_base = smem_u32(dsm);

    float acc[4][4][4];
    #pragma unroll
    for (int mt=0;mt<4;++mt)
        #pragma unroll
        for (int nt=0;nt<4;++nt)
            #pragma unroll
            for (int e=0;e<4;++e) acc[mt][nt][e]=0.f;

    auto stage_issue = [&](int c){
        int p = c/36, rr = c - p*36;
        int tap = rr>>2, icq = rr&3;
        int dy = tap/3, dx = tap - dy*3;
        int pb = p*BB + b;
        unsigned sbase = smem_base + (c%3)*STG_BYTES;
        const float* Asrc = g_WfT + ((size_t)pb*9 + tap)*COUT*CIN + icq*32;
        #pragma unroll
        for (int j=0;j<2;++j){
            int idx = j*NTHR + tid;
            int oc = idx>>3, c8 = idx&7;
            unsigned dst = sbase + oc*128 + ((c8 ^ (oc&7))<<4);
            cp16(dst, Asrc + oc*CIN + c8*4, 16);
        }
        const float* Bsrc = g_xT + (size_t)pb*HW*CIN + icq*32;
        #pragma unroll
        for (int j=0;j<4;++j){
            int idx = j*NTHR + tid;
            int px = idx>>3, c8 = idx&7;
            int pg = px0 + px;
            int y = pg/WW, x = pg - y*WW;
            int iy = y+dy-1, ix = x+dx-1;
            bool ok = ((unsigned)iy<(unsigned)HH) && ((unsigned)ix<(unsigned)WW);
            unsigned dst = sbase + 16384 + px*128 + ((c8 ^ (px&7))<<4);
            cp16(dst, Bsrc + ((size_t)iy*WW + ix)*CIN + c8*4, ok ? 16u : 0u);
        }
        asm volatile("cp.async.commit_group;" ::: "memory");
    };

    stage_issue(0);
    stage_issue(1);
    for (int c=0;c<72;++c){
        asm volatile("cp.async.wait_group 1;" ::: "memory");
        __syncthreads();
        unsigned base = smem_base + (c%3)*STG_BYTES;
        #pragma unroll
        for (int ks=0;ks<4;++ks){
            int kc = ks*2;
            unsigned af[4][4], bf[2][4];
            #pragma unroll
            for (int mt=0;mt<4;++mt){
                int oc_m = wm*64 + mt*16 + rowA;
                int kcm = kc + kselA;
                ldsm4(af[mt], base + oc_m*128 + ((kcm ^ (oc_m&7))<<4));
            }
            #pragma unroll
            for (int q=0;q<2;++q){
                int n_m = wn*32 + q*16 + rowB;
                int kcn = kc + kselB;
                ldsm4(bf[q], base + 16384 + n_m*128 + ((kcn ^ (n_m&7))<<4));
            }
            #pragma unroll
            for (int mt=0;mt<4;++mt)
                #pragma unroll
                for (int nt=0;nt<4;++nt)
                    mma_tf32(acc[mt][nt], af[mt], &bf[nt>>1][(nt&1)*2]);
        }
        __syncthreads();
        if (c+2 < 72) stage_issue(c+2);
    }

    #pragma unroll
    for (int mt=0;mt<4;++mt){
        int oc = wm*64 + mt*16 + g;
        float b0 = sBias[oc], b1 = sBias[oc+8];
        #pragma unroll
        for (int nt=0;nt<4;++nt){
            int n = wn*32 + nt*8 + 2*tg;
            float* o0 = out + ((size_t)b*COUT + oc)*HW + px0 + n;
            float* o1 = out + ((size_t)b*COUT + oc + 8)*HW + px0 + n;
            *(float2*)o0 = make_float2(acc[mt][nt][0]+b0, acc[mt][nt][1]+b0);
            *(float2*)o1 = make_float2(acc[mt][nt][2]+b1, acc[mt][nt][3]+b1);
        }
    }
}

// ---------------- launch ----------------
extern "C" void kernel_launch(void* const* d_in, const int* in_sizes, int n_in,
                              void* d_out, int out_size){
    const float* x0     = (const float*)d_in[0];
    const float* x1     = (const float*)d_in[1];
    const float* fc_w   = (const float*)d_in[2];
    const float* ln_g   = (const float*)d_in[3];
    const float* ln_b   = (const float*)d_in[4];
    const float* ch_w   = (const float*)d_in[5];
    const float* ch_b   = (const float*)d_in[6];
    const float* fl_w   = (const float*)d_in[7];
    const float* fl_b   = (const float*)d_in[8];
    const float* sp_w   = (const float*)d_in[9];
    const float* sp_b   = (const float*)d_in[10];
    const float* kn_w   = (const float*)d_in[11];
    const float* kn_b   = (const float*)d_in[12];
    const float* weight = (const float*)d_in[13];
    const float* mlp_w1 = (const float*)d_in[14];
    const float* mlp_b1 = (const float*)d_in[15];
    const float* mlp_w2 = (const float*)d_in[16];
    const float* mlp_b2 = (const float*)d_in[17];
    const float* fuse_w = (const float*)d_in[18];
    const float* fuse_b = (const float*)d_in[19];
    float* out = (float*)d_out;

    cudaFuncSetAttribute(k_conv, cudaFuncAttributeMaxDynamicSharedMemorySize, SMEM_BYTES);

    k_stats<<<BB*CIN, 256>>>(x0, x1);
    k_att<<<BB, 128>>>(fc_w, ln_g, ln_b, ch_w, ch_b, fl_w, fl_b,
                       sp_w, sp_b, kn_w, kn_b, mlp_w1, mlp_b1, mlp_w2, mlp_b2);
    k_agg<<<dim3(576, PB), 256>>>(weight);
    k_wf <<<dim3(18, PB), 256>>>(fuse_w);
    k_tr <<<dim3(HW/128, CIN/32, PB), 256>>>(x0, x1);
    k_conv<<<dim3(HW/NPX, BB), NTHR, SMEM_BYTES>>>(fuse_b, out);
}

// round 11
// speedup vs baseline: 3.6687x; 1.1084x over previous
#include <cuda_runtime.h>
#include <math.h>

#define BB 8
#define CIN 128
#define COUT 128
#define KN 4
#define HH 160
#define WW 160
#define ATT 16
#define MID 32
#define HW (HH*WW)
#define IKK (CIN*9)
#define PB 16

#define NPX 256
#define NTHR 512
#define STG_BYTES 49152        // per stage: A 16KB + B 32KB
#define SMEM_BYTES (3*STG_BYTES)

__device__ float g_gap0[BB*CIN];
__device__ float g_gap1[BB*CIN];
__device__ float g_fdmean[BB*CIN];
__device__ float g_fdmax[BB*CIN];
__device__ float g_ca[PB*CIN];
__device__ float g_fa[PB*COUT];
__device__ float g_sM[PB*9];
__device__ float g_ka[PB*KN];
__device__ float g_A[PB*COUT*IKK];
// tf32-rounded folded weights, layout [pb][tap][oc][ic]
__device__ __align__(16) float g_WfT[(size_t)PB*9*COUT*CIN];
__device__ __align__(16) float g_xT[(size_t)PB*HW*CIN];  // tf32-rounded NHWC

__device__ __forceinline__ float sigm(float x){ return 1.f/(1.f+expf(-x)); }
__device__ __forceinline__ float to_tf32(float x){
    float r; asm("cvt.rna.tf32.f32 %0, %1;" : "=f"(r) : "f"(x)); return r;
}
__device__ __forceinline__ unsigned smem_u32(const void* p){
    unsigned a;
    asm("{ .reg .u64 t; cvta.to.shared.u64 t, %1; cvt.u32.u64 %0, t; }" : "=r"(a) : "l"(p));
    return a;
}
__device__ __forceinline__ void mma_tf32(float* c, const unsigned* a, const unsigned* b){
    asm volatile(
        "mma.sync.aligned.m16n8k8.row.col.f32.tf32.tf32.f32 "
        "{%0,%1,%2,%3}, {%4,%5,%6,%7}, {%8,%9}, {%0,%1,%2,%3};"
        : "+f"(c[0]), "+f"(c[1]), "+f"(c[2]), "+f"(c[3])
        : "r"(a[0]), "r"(a[1]), "r"(a[2]), "r"(a[3]), "r"(b[0]), "r"(b[1]));
}
__device__ __forceinline__ void ldsm4(unsigned* d, unsigned addr){
    asm volatile("ldmatrix.sync.aligned.m8n8.x4.shared.b16 {%0,%1,%2,%3}, [%4];"
        : "=r"(d[0]),"=r"(d[1]),"=r"(d[2]),"=r"(d[3]) : "r"(addr));
}
__device__ __forceinline__ void cp16(unsigned dst, const void* src, unsigned sz){
    asm volatile("cp.async.ca.shared.global [%0], [%1], 16, %2;"
        :: "r"(dst), "l"(src), "r"(sz) : "memory");
}

// ---------------- k_stats ----------------
__global__ __launch_bounds__(256) void k_stats(const float* __restrict__ x0,
                                               const float* __restrict__ x1){
    int bc = blockIdx.x;
    const float4* p0 = (const float4*)(x0 + (size_t)bc*HW);
    const float4* p1 = (const float4*)(x1 + (size_t)bc*HW);
    float s0=0.f, s1=0.f, mx=-3.0e38f;
    for (int i = threadIdx.x; i < HW/4; i += 256){
        float4 a = p0[i], b = p1[i];
        s0 += (a.x+a.y)+(a.z+a.w);
        s1 += (b.x+b.y)+(b.z+b.w);
        mx = fmaxf(mx, fmaxf(fmaxf(a.x-b.x,a.y-b.y), fmaxf(a.z-b.z,a.w-b.w)));
    }
    #pragma unroll
    for (int off=16; off; off>>=1){
        s0 += __shfl_down_sync(0xffffffffu, s0, off);
        s1 += __shfl_down_sync(0xffffffffu, s1, off);
        mx  = fmaxf(mx, __shfl_down_sync(0xffffffffu, mx, off));
    }
    __shared__ float r0[8], r1[8], rm[8];
    int w = threadIdx.x >> 5;
    if ((threadIdx.x & 31) == 0){ r0[w]=s0; r1[w]=s1; rm[w]=mx; }
    __syncthreads();
    if (threadIdx.x == 0){
        float S0=0.f, S1=0.f, M=-3.0e38f;
        #pragma unroll
        for (int i=0;i<8;++i){ S0+=r0[i]; S1+=r1[i]; M=fmaxf(M, rm[i]); }
        const float inv = 1.f/(float)HW;
        g_gap0[bc]=S0*inv; g_gap1[bc]=S1*inv; g_fdmean[bc]=(S0-S1)*inv; g_fdmax[bc]=M;
    }
}

// ---------------- k_att ----------------
__global__ __launch_bounds__(128) void k_att(
    const float* __restrict__ fc_w,  const float* __restrict__ ln_g,  const float* __restrict__ ln_b,
    const float* __restrict__ ch_w,  const float* __restrict__ ch_b,
    const float* __restrict__ fl_w,  const float* __restrict__ fl_b,
    const float* __restrict__ sp_w,  const float* __restrict__ sp_b,
    const float* __restrict__ kn_w,  const float* __restrict__ kn_b,
    const float* __restrict__ mlp_w1,const float* __restrict__ mlp_b1,
    const float* __restrict__ mlp_w2,const float* __restrict__ mlp_b2)
{
    int b = blockIdx.x, tid = threadIdx.x;
    __shared__ float gA[128], gB[128], yv[ATT], hs[MID], mfd[9], kl[KN];
    gA[tid] = g_fdmean[b*CIN + tid];
    gB[tid] = g_fdmax [b*CIN + tid];
    __syncthreads();
    if (tid < MID){
        float sa_ = mlp_b1[tid], sm_ = mlp_b1[tid];
        for (int c=0;c<CIN;++c){ float w = mlp_w1[tid*CIN+c]; sa_ += w*gA[c]; sm_ += w*gB[c]; }
        hs[tid] = fmaxf(sa_,0.f) + fmaxf(sm_,0.f);
    }
    __syncthreads();
    if (tid < 9){
        float z = 2.f*mlp_b2[tid];
        for (int t=0;t<MID;++t) z += mlp_w2[tid*MID+t]*hs[t];
        mfd[tid] = sigm(z);
    }
    for (int p=0;p<2;++p){
        __syncthreads();
        gA[tid] = (p ? g_gap1 : g_gap0)[b*CIN + tid];
        __syncthreads();
        if (tid < ATT){
            float v = 0.f;
            for (int c=0;c<CIN;++c) v += fc_w[tid*CIN+c]*gA[c];
            yv[tid] = v;
        }
        __syncthreads();
        if (tid == 0){
            float mu = 0.f;
            for (int j=0;j<ATT;++j) mu += yv[j];
            mu *= (1.f/ATT);
            float var = 0.f;
            for (int j=0;j<ATT;++j){ float d = yv[j]-mu; var += d*d; }
            var *= (1.f/ATT);
            float inv = rsqrtf(var + 1e-5f);
            for (int j=0;j<ATT;++j)
                yv[j] = fmaxf(0.f, (yv[j]-mu)*inv*ln_g[j] + ln_b[j]);
        }
        __syncthreads();
        {
            float ac = ch_b[tid], af = fl_b[tid];
            for (int j=0;j<ATT;++j){ ac += ch_w[tid*ATT+j]*yv[j]; af += fl_w[tid*ATT+j]*yv[j]; }
            g_ca[(p*BB+b)*CIN  + tid] = sigm(ac);
            g_fa[(p*BB+b)*COUT + tid] = sigm(af);
        }
        if (tid < 9){
            float s = sp_b[tid];
            for (int j=0;j<ATT;++j) s += sp_w[tid*ATT+j]*yv[j];
            g_sM[(p*BB+b)*9 + tid] = sigm(s)*mfd[tid];
        }
        if (tid < KN){
            float l = kn_b[tid];
            for (int j=0;j<ATT;++j) l += kn_w[tid*ATT+j]*yv[j];
            kl[tid] = l;
        }
        __syncthreads();
        if (tid == 0){
            float m = fmaxf(fmaxf(kl[0],kl[1]), fmaxf(kl[2],kl[3]));
            float e0=expf(kl[0]-m), e1=expf(kl[1]-m), e2=expf(kl[2]-m), e3=expf(kl[3]-m);
            float s = e0+e1+e2+e3;
            g_ka[(p*BB+b)*KN+0]=e0/s; g_ka[(p*BB+b)*KN+1]=e1/s;
            g_ka[(p*BB+b)*KN+2]=e2/s; g_ka[(p*BB+b)*KN+3]=e3/s;
        }
    }
}

// ---------------- k_agg ----------------
__global__ __launch_bounds__(256) void k_agg(const float* __restrict__ weight){
    int pb  = blockIdx.y;
    int idx = blockIdx.x*256 + threadIdx.x;
    int c   = idx / IKK;
    float k0=g_ka[pb*KN+0], k1=g_ka[pb*KN+1], k2=g_ka[pb*KN+2], k3=g_ka[pb*KN+3];
    const float* w = weight + idx;
    float acc = k0*w[0] + k1*w[COUT*IKK] + k2*w[2*COUT*IKK] + k3*w[3*COUT*IKK];
    g_A[pb*(COUT*IKK) + idx] = acc * g_fa[pb*COUT + c];
}

// ---------------- k_wf : fuse-GEMM + scales -> tf32 [tap][oc][ic] ----------
__global__ __launch_bounds__(256) void k_wf(const float* __restrict__ fuse_w){
    int pb = blockIdx.y, p = pb >> 3;
    int nt = blockIdx.x;
    int tid = threadIdx.x;
    int to = tid & 15, tn = tid >> 4;
    __shared__ __align__(16) float Fs[16][128];
    __shared__ __align__(16) float As[16][64];
    float acc[8][4];
    #pragma unroll
    for (int o=0;o<8;++o)
        #pragma unroll
        for (int n=0;n<4;++n) acc[o][n]=0.f;
    const float* Abase = g_A + (size_t)pb*(COUT*IKK);
    for (int ck=0; ck<8; ++ck){
        __syncthreads();
        #pragma unroll
        for (int j=0;j<8;++j){
            int l = j*256 + tid; int o = l & 127, cc = l >> 7;
            Fs[cc][o] = fuse_w[o*(2*COUT) + p*COUT + ck*16 + cc];
        }
        #pragma unroll
        for (int j=0;j<4;++j){
            int l = j*256 + tid; int nn = l & 63, cc = l >> 6;
            As[cc][nn] = Abase[(ck*16+cc)*IKK + nt*64 + nn];
        }
        __syncthreads();
        #pragma unroll
        for (int cc=0; cc<16; ++cc){
            float4 av = *(const float4*)&As[cc][tn*4];
            float a_[4] = {av.x, av.y, av.z, av.w};
            float4 f0 = *(const float4*)&Fs[cc][to*8];
            float4 f1 = *(const float4*)&Fs[cc][to*8+4];
            float f_[8] = {f0.x,f0.y,f0.z,f0.w, f1.x,f1.y,f1.z,f1.w};
            #pragma unroll
            for (int o=0;o<8;++o)
                #pragma unroll
                for (int n=0;n<4;++n)
                    acc[o][n] = fmaf(f_[o], a_[n], acc[o][n]);
        }
    }
    float* Wbase = g_WfT + (size_t)pb*9*COUT*CIN;
    const float* cap = g_ca + pb*CIN;
    const float* sMp = g_sM + pb*9;
    #pragma unroll
    for (int n=0;n<4;++n){
        int ikk = nt*64 + tn*4 + n;
        int ic = ikk/9, tap = ikk - ic*9;
        float sc = cap[ic]*sMp[tap];
        #pragma unroll
        for (int o=0;o<8;++o){
            int oc = to*8 + o;
            Wbase[((size_t)tap*COUT + oc)*CIN + ic] = to_tf32(acc[o][n]*sc);
        }
    }
}

// ---------------- k_tr : NCHW fp32 -> NHWC tf32-rounded ----------------
__global__ __launch_bounds__(256) void k_tr(const float* __restrict__ x0,
                                            const float* __restrict__ x1){
    int px0 = blockIdx.x*128, ic0 = blockIdx.y*32, z = blockIdx.z;
    const float* src = (z >= 8 ? x1 : x0) + ((size_t)(z&7)*CIN + ic0)*HW + px0;
    __shared__ float t[32][129];
    int tid = threadIdx.x, lane = tid & 31, w = tid >> 5;
    #pragma unroll
    for (int i=0;i<4;++i){
        int ic = w + i*8;
        float4 v = *(const float4*)(src + (size_t)ic*HW + lane*4);
        t[ic][lane*4+0]=v.x; t[ic][lane*4+1]=v.y; t[ic][lane*4+2]=v.z; t[ic][lane*4+3]=v.w;
    }
    __syncthreads();
    int px = tid >> 1, icg = (tid & 1)*16;
    float* dst = g_xT + ((size_t)z*HW + px0 + px)*CIN + ic0 + icg;
    #pragma unroll
    for (int j=0;j<4;++j){
        float4 v;
        v.x = to_tf32(t[icg+4*j+0][px]);
        v.y = to_tf32(t[icg+4*j+1][px]);
        v.z = to_tf32(t[icg+4*j+2][px]);
        v.w = to_tf32(t[icg+4*j+3][px]);
        *(float4*)(dst + 4*j) = v;
    }
}

// ---------------- k_conv : tf32 mma.sync, hoisted staging, 3-stage ----------
__global__ __launch_bounds__(NTHR) void k_conv(const float* __restrict__ fuse_b,
                                               float* __restrict__ out){
    extern __shared__ float dsm[];
    __shared__ float sBias[128];
    int b = blockIdx.y;
    int px0 = blockIdx.x*NPX;
    int tid = threadIdx.x;
    int lane = tid & 31, wid = tid >> 5;
    int wm = wid >> 3, wn = wid & 7;     // warp: 64 oc x 32 px
    int g = lane >> 2, tg = lane & 3;
    int sel = lane >> 3, r8 = lane & 7;
    int rowA = r8 + ((sel & 1) << 3), kselA = sel >> 1;
    int rowB = r8 + ((sel >> 1) << 3), kselB = sel & 1;
    if (tid < 128) sBias[tid] = fuse_b[tid];
    unsigned smem_base = smem_u32(dsm);

    // ---- hoisted staging geometry (loop-invariant) ----
    unsigned dstA[2]; int srcA[2];              // element offsets
    #pragma unroll
    for (int j=0;j<2;++j){
        int idx = j*NTHR + tid;
        int oc = idx>>3, c8 = idx&7;
        dstA[j] = oc*128 + ((c8 ^ (oc&7))<<4);
        srcA[j] = oc*CIN + c8*4;
    }
    unsigned dstB[4]; int srcB[4]; unsigned bmask[4];
    #pragma unroll
    for (int j=0;j<4;++j){
        int idx = j*NTHR + tid;
        int px = idx>>3, c8 = idx&7;
        dstB[j] = 16384 + px*128 + ((c8 ^ (px&7))<<4);
        int pg = px0 + px;
        int y = pg/WW, x = pg - y*WW;
        srcB[j] = (y*WW + x - WW - 1)*CIN + c8*4;   // dy=dx=0 corner
        unsigned m = 0;
        #pragma unroll
        for (int tap=0;tap<9;++tap){
            int dy = tap/3, dx = tap - dy*3;
            bool ok = ((unsigned)(y+dy-1) < (unsigned)HH) && ((unsigned)(x+dx-1) < (unsigned)WW);
            m |= (ok ? 1u : 0u) << tap;
        }
        bmask[j] = m;
    }

    float acc[4][4][4];
    #pragma unroll
    for (int mt=0;mt<4;++mt)
        #pragma unroll
        for (int nt=0;nt<4;++nt)
            #pragma unroll
            for (int e=0;e<4;++e) acc[mt][nt][e]=0.f;

    auto stage_issue = [&](int c, int slot){
        int p = (c>=36) ? 1 : 0;
        int rr = c - p*36;
        int tap = rr>>2, icq = rr&3;
        int dy = tap/3, dx = tap - dy*3;
        int pb = p*BB + b;
        unsigned sbase = smem_base + slot*STG_BYTES;
        const float* Ab = g_WfT + ((size_t)pb*9 + tap)*COUT*CIN + icq*32;
        #pragma unroll
        for (int j=0;j<2;++j)
            cp16(sbase + dstA[j], Ab + srcA[j], 16);
        const float* Bb = g_xT + (size_t)pb*HW*CIN + (dy*WW + dx)*CIN + icq*32;
        #pragma unroll
        for (int j=0;j<4;++j)
            cp16(sbase + dstB[j], Bb + srcB[j], ((bmask[j]>>tap)&1) ? 16u : 0u);
        asm volatile("cp.async.commit_group;" ::: "memory");
    };

    stage_issue(0, 0);
    stage_issue(1, 1);
    int scur = 0, snext = 2;
    for (int c=0;c<72;++c){
        asm volatile("cp.async.wait_group 1;" ::: "memory");
        __syncthreads();
        if (c+2 < 72) stage_issue(c+2, snext);
        unsigned base = smem_base + scur*STG_BYTES;
        #pragma unroll
        for (int ks=0;ks<4;++ks){
            int kc = ks*2;
            unsigned af[4][4], bf[2][4];
            #pragma unroll
            for (int mt=0;mt<4;++mt){
                int oc_m = wm*64 + mt*16 + rowA;
                int kcm = kc + kselA;
                ldsm4(af[mt], base + oc_m*128 + ((kcm ^ (oc_m&7))<<4));
            }
            #pragma unroll
            for (int q=0;q<2;++q){
                int n_m = wn*32 + q*16 + rowB;
                int kcn = kc + kselB;
                ldsm4(bf[q], base + 16384 + n_m*128 + ((kcn ^ (n_m&7))<<4));
            }
            #pragma unroll
            for (int mt=0;mt<4;++mt)
                #pragma unroll
                for (int nt=0;nt<4;++nt)
                    mma_tf32(acc[mt][nt], af[mt], &bf[nt>>1][(nt&1)*2]);
        }
        scur = (scur==2) ? 0 : scur+1;
        snext = (snext==2) ? 0 : snext+1;
    }

    #pragma unroll
    for (int mt=0;mt<4;++mt){
        int oc = wm*64 + mt*16 + g;
        float b0 = sBias[oc], b1 = sBias[oc+8];
        #pragma unroll
        for (int nt=0;nt<4;++nt){
            int n = wn*32 + nt*8 + 2*tg;
            float* o0 = out + ((size_t)b*COUT + oc)*HW + px0 + n;
            float* o1 = out + ((size_t)b*COUT + oc + 8)*HW + px0 + n;
            *(float2*)o0 = make_float2(acc[mt][nt][0]+b0, acc[mt][nt][1]+b0);
            *(float2*)o1 = make_float2(acc[mt][nt][2]+b1, acc[mt][nt][3]+b1);
        }
    }
}

// ---------------- launch ----------------
extern "C" void kernel_launch(void* const* d_in, const int* in_sizes, int n_in,
                              void* d_out, int out_size){
    const float* x0     = (const float*)d_in[0];
    const float* x1     = (const float*)d_in[1];
    const float* fc_w   = (const float*)d_in[2];
    const float* ln_g   = (const float*)d_in[3];
    const float* ln_b   = (const float*)d_in[4];
    const float* ch_w   = (const float*)d_in[5];
    const float* ch_b   = (const float*)d_in[6];
    const float* fl_w   = (const float*)d_in[7];
    const float* fl_b   = (const float*)d_in[8];
    const float* sp_w   = (const float*)d_in[9];
    const float* sp_b   = (const float*)d_in[10];
    const float* kn_w   = (const float*)d_in[11];
    const float* kn_b   = (const float*)d_in[12];
    const float* weight = (const float*)d_in[13];
    const float* mlp_w1 = (const float*)d_in[14];
    const float* mlp_b1 = (const float*)d_in[15];
    const float* mlp_w2 = (const float*)d_in[16];
    const float* mlp_b2 = (const float*)d_in[17];
    const float* fuse_w = (const float*)d_in[18];
    const float* fuse_b = (const float*)d_in[19];
    float* out = (float*)d_out;

    cudaFuncSetAttribute(k_conv, cudaFuncAttributeMaxDynamicSharedMemorySize, SMEM_BYTES);

    k_stats<<<BB*CIN, 256>>>(x0, x1);
    k_att<<<BB, 128>>>(fc_w, ln_g, ln_b, ch_w, ch_b, fl_w, fl_b,
                       sp_w, sp_b, kn_w, kn_b, mlp_w1, mlp_b1, mlp_w2, mlp_b2);
    k_agg<<<dim3(576, PB), 256>>>(weight);
    k_wf <<<dim3(18, PB), 256>>>(fuse_w);
    k_tr <<<dim3(HW/128, CIN/32, PB), 256>>>(x0, x1);
    k_conv<<<dim3(HW/NPX, BB), NTHR, SMEM_BYTES>>>(fuse_b, out);
}

// round 12
// speedup vs baseline: 3.8052x; 1.0372x over previous
#include <cuda_runtime.h>
#include <math.h>

#define BB 8
#define CIN 128
#define COUT 128
#define KN 4
#define HH 160
#define WW 160
#define ATT 16
#define MID 32
#define HW (HH*WW)
#define IKK (CIN*9)
#define PB 16

#define NPX 256
#define NTHR 512
#define STG_BYTES 98304        // per stage: A 32KB + B 64KB (K-chunk = 64)
#define SMEM_BYTES (2*STG_BYTES)

__device__ float g_gap0[BB*CIN];
__device__ float g_gap1[BB*CIN];
__device__ float g_fdmean[BB*CIN];
__device__ float g_fdmax[BB*CIN];
__device__ float g_ca[PB*CIN];
__device__ float g_fa[PB*COUT];
__device__ float g_sM[PB*9];
__device__ float g_ka[PB*KN];
__device__ float g_A[PB*COUT*IKK];
__device__ float g_fuseT[2*COUT*COUT];          // [c(256)][o(128)] transposed fuse
// tf32-rounded folded weights, layout [pb][tap][oc][ic]
__device__ __align__(16) float g_WfT[(size_t)PB*9*COUT*CIN];
__device__ __align__(16) float g_xT[(size_t)PB*HW*CIN];  // tf32-rounded NHWC

__device__ __forceinline__ float sigm(float x){ return 1.f/(1.f+expf(-x)); }
__device__ __forceinline__ float to_tf32(float x){
    float r; asm("cvt.rna.tf32.f32 %0, %1;" : "=f"(r) : "f"(x)); return r;
}
__device__ __forceinline__ unsigned smem_u32(const void* p){
    unsigned a;
    asm("{ .reg .u64 t; cvta.to.shared.u64 t, %1; cvt.u32.u64 %0, t; }" : "=r"(a) : "l"(p));
    return a;
}
__device__ __forceinline__ void mma_tf32(float* c, const unsigned* a, const unsigned* b){
    asm volatile(
        "mma.sync.aligned.m16n8k8.row.col.f32.tf32.tf32.f32 "
        "{%0,%1,%2,%3}, {%4,%5,%6,%7}, {%8,%9}, {%0,%1,%2,%3};"
        : "+f"(c[0]), "+f"(c[1]), "+f"(c[2]), "+f"(c[3])
        : "r"(a[0]), "r"(a[1]), "r"(a[2]), "r"(a[3]), "r"(b[0]), "r"(b[1]));
}
__device__ __forceinline__ void ldsm4(unsigned* d, unsigned addr){
    asm volatile("ldmatrix.sync.aligned.m8n8.x4.shared.b16 {%0,%1,%2,%3}, [%4];"
        : "=r"(d[0]),"=r"(d[1]),"=r"(d[2]),"=r"(d[3]) : "r"(addr));
}
__device__ __forceinline__ void cp16(unsigned dst, const void* src, unsigned sz){
    asm volatile("cp.async.ca.shared.global [%0], [%1], 16, %2;"
        :: "r"(dst), "l"(src), "r"(sz) : "memory");
}

// ---------------- k_stats ----------------
__global__ __launch_bounds__(256) void k_stats(const float* __restrict__ x0,
                                               const float* __restrict__ x1){
    int bc = blockIdx.x;
    const float4* p0 = (const float4*)(x0 + (size_t)bc*HW);
    const float4* p1 = (const float4*)(x1 + (size_t)bc*HW);
    float s0=0.f, s1=0.f, mx=-3.0e38f;
    for (int i = threadIdx.x; i < HW/4; i += 256){
        float4 a = p0[i], b = p1[i];
        s0 += (a.x+a.y)+(a.z+a.w);
        s1 += (b.x+b.y)+(b.z+b.w);
        mx = fmaxf(mx, fmaxf(fmaxf(a.x-b.x,a.y-b.y), fmaxf(a.z-b.z,a.w-b.w)));
    }
    #pragma unroll
    for (int off=16; off; off>>=1){
        s0 += __shfl_down_sync(0xffffffffu, s0, off);
        s1 += __shfl_down_sync(0xffffffffu, s1, off);
        mx  = fmaxf(mx, __shfl_down_sync(0xffffffffu, mx, off));
    }
    __shared__ float r0[8], r1[8], rm[8];
    int w = threadIdx.x >> 5;
    if ((threadIdx.x & 31) == 0){ r0[w]=s0; r1[w]=s1; rm[w]=mx; }
    __syncthreads();
    if (threadIdx.x == 0){
        float S0=0.f, S1=0.f, M=-3.0e38f;
        #pragma unroll
        for (int i=0;i<8;++i){ S0+=r0[i]; S1+=r1[i]; M=fmaxf(M, rm[i]); }
        const float inv = 1.f/(float)HW;
        g_gap0[bc]=S0*inv; g_gap1[bc]=S1*inv; g_fdmean[bc]=(S0-S1)*inv; g_fdmax[bc]=M;
    }
}

// ---------------- k_att ----------------
__global__ __launch_bounds__(128) void k_att(
    const float* __restrict__ fc_w,  const float* __restrict__ ln_g,  const float* __restrict__ ln_b,
    const float* __restrict__ ch_w,  const float* __restrict__ ch_b,
    const float* __restrict__ fl_w,  const float* __restrict__ fl_b,
    const float* __restrict__ sp_w,  const float* __restrict__ sp_b,
    const float* __restrict__ kn_w,  const float* __restrict__ kn_b,
    const float* __restrict__ mlp_w1,const float* __restrict__ mlp_b1,
    const float* __restrict__ mlp_w2,const float* __restrict__ mlp_b2)
{
    int b = blockIdx.x, tid = threadIdx.x;
    __shared__ float gA[128], gB[128], yv[ATT], hs[MID], mfd[9], kl[KN];
    gA[tid] = g_fdmean[b*CIN + tid];
    gB[tid] = g_fdmax [b*CIN + tid];
    __syncthreads();
    if (tid < MID){
        float sa_ = mlp_b1[tid], sm_ = mlp_b1[tid];
        for (int c=0;c<CIN;++c){ float w = mlp_w1[tid*CIN+c]; sa_ += w*gA[c]; sm_ += w*gB[c]; }
        hs[tid] = fmaxf(sa_,0.f) + fmaxf(sm_,0.f);
    }
    __syncthreads();
    if (tid < 9){
        float z = 2.f*mlp_b2[tid];
        for (int t=0;t<MID;++t) z += mlp_w2[tid*MID+t]*hs[t];
        mfd[tid] = sigm(z);
    }
    for (int p=0;p<2;++p){
        __syncthreads();
        gA[tid] = (p ? g_gap1 : g_gap0)[b*CIN + tid];
        __syncthreads();
        if (tid < ATT){
            float v = 0.f;
            for (int c=0;c<CIN;++c) v += fc_w[tid*CIN+c]*gA[c];
            yv[tid] = v;
        }
        __syncthreads();
        if (tid == 0){
            float mu = 0.f;
            for (int j=0;j<ATT;++j) mu += yv[j];
            mu *= (1.f/ATT);
            float var = 0.f;
            for (int j=0;j<ATT;++j){ float d = yv[j]-mu; var += d*d; }
            var *= (1.f/ATT);
            float inv = rsqrtf(var + 1e-5f);
            for (int j=0;j<ATT;++j)
                yv[j] = fmaxf(0.f, (yv[j]-mu)*inv*ln_g[j] + ln_b[j]);
        }
        __syncthreads();
        {
            float ac = ch_b[tid], af = fl_b[tid];
            for (int j=0;j<ATT;++j){ ac += ch_w[tid*ATT+j]*yv[j]; af += fl_w[tid*ATT+j]*yv[j]; }
            g_ca[(p*BB+b)*CIN  + tid] = sigm(ac);
            g_fa[(p*BB+b)*COUT + tid] = sigm(af);
        }
        if (tid < 9){
            float s = sp_b[tid];
            for (int j=0;j<ATT;++j) s += sp_w[tid*ATT+j]*yv[j];
            g_sM[(p*BB+b)*9 + tid] = sigm(s)*mfd[tid];
        }
        if (tid < KN){
            float l = kn_b[tid];
            for (int j=0;j<ATT;++j) l += kn_w[tid*ATT+j]*yv[j];
            kl[tid] = l;
        }
        __syncthreads();
        if (tid == 0){
            float m = fmaxf(fmaxf(kl[0],kl[1]), fmaxf(kl[2],kl[3]));
            float e0=expf(kl[0]-m), e1=expf(kl[1]-m), e2=expf(kl[2]-m), e3=expf(kl[3]-m);
            float s = e0+e1+e2+e3;
            g_ka[(p*BB+b)*KN+0]=e0/s; g_ka[(p*BB+b)*KN+1]=e1/s;
            g_ka[(p*BB+b)*KN+2]=e2/s; g_ka[(p*BB+b)*KN+3]=e3/s;
        }
    }
}

// ---------------- k_agg ----------------
__global__ __launch_bounds__(256) void k_agg(const float* __restrict__ weight){
    int pb  = blockIdx.y;
    int idx = blockIdx.x*256 + threadIdx.x;
    int c   = idx / IKK;
    float k0=g_ka[pb*KN+0], k1=g_ka[pb*KN+1], k2=g_ka[pb*KN+2], k3=g_ka[pb*KN+3];
    const float* w = weight + idx;
    float acc = k0*w[0] + k1*w[COUT*IKK] + k2*w[2*COUT*IKK] + k3*w[3*COUT*IKK];
    g_A[pb*(COUT*IKK) + idx] = acc * g_fa[pb*COUT + c];
}

// ---------------- k_ftr : transpose fuse_w -> [c][o] ----------------
__global__ __launch_bounds__(128) void k_ftr(const float* __restrict__ fuse_w){
    int c = blockIdx.x, o = threadIdx.x;
    g_fuseT[c*COUT + o] = fuse_w[o*(2*COUT) + c];
}

// ---------------- k_wf : fuse-GEMM + scales -> tf32 [tap][oc][ic] ----------
__global__ __launch_bounds__(256) void k_wf(){
    int pb = blockIdx.y, p = pb >> 3;
    int nt = blockIdx.x;
    int tid = threadIdx.x;
    int to = tid & 15, tn = tid >> 4;
    __shared__ __align__(16) float Fs[16][128];
    __shared__ __align__(16) float As[16][64];
    float acc[8][4];
    #pragma unroll
    for (int o=0;o<8;++o)
        #pragma unroll
        for (int n=0;n<4;++n) acc[o][n]=0.f;
    const float* Abase = g_A + (size_t)pb*(COUT*IKK);
    for (int ck=0; ck<8; ++ck){
        __syncthreads();
        #pragma unroll
        for (int j=0;j<8;++j){          // coalesced: o contiguous in g_fuseT
            int l = j*256 + tid; int o = l & 127, cc = l >> 7;
            Fs[cc][o] = g_fuseT[(p*COUT + ck*16 + cc)*COUT + o];
        }
        #pragma unroll
        for (int j=0;j<4;++j){
            int l = j*256 + tid; int nn = l & 63, cc = l >> 6;
            As[cc][nn] = Abase[(ck*16+cc)*IKK + nt*64 + nn];
        }
        __syncthreads();
        #pragma unroll
        for (int cc=0; cc<16; ++cc){
            float4 av = *(const float4*)&As[cc][tn*4];
            float a_[4] = {av.x, av.y, av.z, av.w};
            float4 f0 = *(const float4*)&Fs[cc][to*8];
            float4 f1 = *(const float4*)&Fs[cc][to*8+4];
            float f_[8] = {f0.x,f0.y,f0.z,f0.w, f1.x,f1.y,f1.z,f1.w};
            #pragma unroll
            for (int o=0;o<8;++o)
                #pragma unroll
                for (int n=0;n<4;++n)
                    acc[o][n] = fmaf(f_[o], a_[n], acc[o][n]);
        }
    }
    float* Wbase = g_WfT + (size_t)pb*9*COUT*CIN;
    const float* cap = g_ca + pb*CIN;
    const float* sMp = g_sM + pb*9;
    #pragma unroll
    for (int n=0;n<4;++n){
        int ikk = nt*64 + tn*4 + n;
        int ic = ikk/9, tap = ikk - ic*9;
        float sc = cap[ic]*sMp[tap];
        #pragma unroll
        for (int o=0;o<8;++o){
            int oc = to*8 + o;
            Wbase[((size_t)tap*COUT + oc)*CIN + ic] = to_tf32(acc[o][n]*sc);
        }
    }
}

// ---------------- k_tr : NCHW fp32 -> NHWC tf32-rounded ----------------
__global__ __launch_bounds__(256) void k_tr(const float* __restrict__ x0,
                                            const float* __restrict__ x1){
    int px0 = blockIdx.x*128, ic0 = blockIdx.y*32, z = blockIdx.z;
    const float* src = (z >= 8 ? x1 : x0) + ((size_t)(z&7)*CIN + ic0)*HW + px0;
    __shared__ float t[32][129];
    int tid = threadIdx.x, lane = tid & 31, w = tid >> 5;
    #pragma unroll
    for (int i=0;i<4;++i){
        int ic = w + i*8;
        float4 v = *(const float4*)(src + (size_t)ic*HW + lane*4);
        t[ic][lane*4+0]=v.x; t[ic][lane*4+1]=v.y; t[ic][lane*4+2]=v.z; t[ic][lane*4+3]=v.w;
    }
    __syncthreads();
    int px = tid >> 1, icg = (tid & 1)*16;
    float* dst = g_xT + ((size_t)z*HW + px0 + px)*CIN + ic0 + icg;
    #pragma unroll
    for (int j=0;j<4;++j){
        float4 v;
        v.x = to_tf32(t[icg+4*j+0][px]);
        v.y = to_tf32(t[icg+4*j+1][px]);
        v.z = to_tf32(t[icg+4*j+2][px]);
        v.w = to_tf32(t[icg+4*j+3][px]);
        *(float4*)(dst + 4*j) = v;
    }
}

// ---------------- k_conv : tf32 mma.sync, K-chunk 64, 2-stage ----------
__global__ __launch_bounds__(NTHR) void k_conv(const float* __restrict__ fuse_b,
                                               float* __restrict__ out){
    extern __shared__ float dsm[];
    __shared__ float sBias[128];
    int b = blockIdx.y;
    int px0 = blockIdx.x*NPX;
    int tid = threadIdx.x;
    int lane = tid & 31, wid = tid >> 5;
    int wm = wid >> 3, wn = wid & 7;     // warp: 64 oc x 32 px
    int g = lane >> 2, tg = lane & 3;
    int sel = lane >> 3, r8 = lane & 7;
    int rowA = r8 + ((sel & 1) << 3), kselA = sel >> 1;
    int rowB = r8 + ((sel >> 1) << 3), kselB = sel & 1;
    if (tid < 128) sBias[tid] = fuse_b[tid];
    unsigned smem_base = smem_u32(dsm);

    // hoisted ldsm row offsets (XOR operand == r8 for all tiles)
    unsigned aoff[4], boff[2];
    #pragma unroll
    for (int mt=0;mt<4;++mt) aoff[mt] = (wm*64 + mt*16 + rowA)*256;
    #pragma unroll
    for (int q=0;q<2;++q)    boff[q] = 32768 + (wn*32 + q*16 + rowB)*256;

    // ---- hoisted staging geometry ----
    unsigned dstA[4]; int srcA[4];
    #pragma unroll
    for (int j=0;j<4;++j){
        int idx = j*NTHR + tid;
        int oc = idx>>4, c16 = idx&15;
        dstA[j] = oc*256 + ((c16 ^ (oc&7))<<4);
        srcA[j] = oc*CIN + c16*4;
    }
    unsigned dstB[8]; int srcB[8]; unsigned bmask[8];
    #pragma unroll
    for (int j=0;j<8;++j){
        int idx = j*NTHR + tid;
        int px = idx>>4, c16 = idx&15;
        dstB[j] = 32768 + px*256 + ((c16 ^ (px&7))<<4);
        int pg = px0 + px;
        int y = pg/WW, x = pg - y*WW;
        srcB[j] = (y*WW + x - WW - 1)*CIN + c16*4;
        unsigned m = 0;
        #pragma unroll
        for (int tap=0;tap<9;++tap){
            int dy = tap/3, dx = tap - dy*3;
            bool ok = ((unsigned)(y+dy-1) < (unsigned)HH) && ((unsigned)(x+dx-1) < (unsigned)WW);
            m |= (ok ? 1u : 0u) << tap;
        }
        bmask[j] = m;
    }

    float acc[4][4][4];
    #pragma unroll
    for (int mt=0;mt<4;++mt)
        #pragma unroll
        for (int nt=0;nt<4;++nt)
            #pragma unroll
            for (int e=0;e<4;++e) acc[mt][nt][e]=0.f;

    auto stage_issue = [&](int c, int slot){
        int p = (c>=18) ? 1 : 0;
        int rr = c - p*18;
        int tap = rr>>1, ich = rr&1;
        int dy = tap/3, dx = tap - dy*3;
        int pb = p*BB + b;
        unsigned sbase = smem_base + slot*STG_BYTES;
        const float* Ab = g_WfT + ((size_t)pb*9 + tap)*COUT*CIN + ich*64;
        #pragma unroll
        for (int j=0;j<4;++j)
            cp16(sbase + dstA[j], Ab + srcA[j], 16);
        const float* Bb = g_xT + (size_t)pb*HW*CIN + (dy*WW + dx)*CIN + ich*64;
        unsigned tb = 1u << tap;
        #pragma unroll
        for (int j=0;j<8;++j)
            cp16(sbase + dstB[j], Bb + srcB[j], (bmask[j] & tb) ? 16u : 0u);
        asm volatile("cp.async.commit_group;" ::: "memory");
    };

    stage_issue(0, 0);
    stage_issue(1, 1);
    for (int c=0;c<36;++c){
        if (c < 34) asm volatile("cp.async.wait_group 1;" ::: "memory");
        else        asm volatile("cp.async.wait_group 0;" ::: "memory");
        __syncthreads();
        unsigned base = smem_base + (c&1)*STG_BYTES;
        #pragma unroll
        for (int ks=0;ks<8;++ks){
            int kc = ks*2;
            unsigned kA = (unsigned)(((kc + kselA) ^ r8) << 4);
            unsigned kB = (unsigned)(((kc + kselB) ^ r8) << 4);
            unsigned af[4][4], bf[2][4];
            #pragma unroll
            for (int mt=0;mt<4;++mt) ldsm4(af[mt], base + aoff[mt] + kA);
            #pragma unroll
            for (int q=0;q<2;++q)    ldsm4(bf[q],  base + boff[q] + kB);
            #pragma unroll
            for (int mt=0;mt<4;++mt)
                #pragma unroll
                for (int nt=0;nt<4;++nt)
                    mma_tf32(acc[mt][nt], af[mt], &bf[nt>>1][(nt&1)*2]);
        }
        __syncthreads();
        if (c+2 < 36) stage_issue(c+2, c&1);
    }

    #pragma unroll
    for (int mt=0;mt<4;++mt){
        int oc = wm*64 + mt*16 + g;
        float b0 = sBias[oc], b1 = sBias[oc+8];
        #pragma unroll
        for (int nt=0;nt<4;++nt){
            int n = wn*32 + nt*8 + 2*tg;
            float* o0 = out + ((size_t)b*COUT + oc)*HW + px0 + n;
            float* o1 = out + ((size_t)b*COUT + oc + 8)*HW + px0 + n;
            *(float2*)o0 = make_float2(acc[mt][nt][0]+b0, acc[mt][nt][1]+b0);
            *(float2*)o1 = make_float2(acc[mt][nt][2]+b1, acc[mt][nt][3]+b1);
        }
    }
}

// ---------------- launch ----------------
extern "C" void kernel_launch(void* const* d_in, const int* in_sizes, int n_in,
                              void* d_out, int out_size){
    const float* x0     = (const float*)d_in[0];
    const float* x1     = (const float*)d_in[1];
    const float* fc_w   = (const float*)d_in[2];
    const float* ln_g   = (const float*)d_in[3];
    const float* ln_b   = (const float*)d_in[4];
    const float* ch_w   = (const float*)d_in[5];
    const float* ch_b   = (const float*)d_in[6];
    const float* fl_w   = (const float*)d_in[7];
    const float* fl_b   = (const float*)d_in[8];
    const float* sp_w   = (const float*)d_in[9];
    const float* sp_b   = (const float*)d_in[10];
    const float* kn_w   = (const float*)d_in[11];
    const float* kn_b   = (const float*)d_in[12];
    const float* weight = (const float*)d_in[13];
    const float* mlp_w1 = (const float*)d_in[14];
    const float* mlp_b1 = (const float*)d_in[15];
    const float* mlp_w2 = (const float*)d_in[16];
    const float* mlp_b2 = (const float*)d_in[17];
    const float* fuse_w = (const float*)d_in[18];
    const float* fuse_b = (const float*)d_in[19];
    float* out = (float*)d_out;

    cudaFuncSetAttribute(k_conv, cudaFuncAttributeMaxDynamicSharedMemorySize, SMEM_BYTES);

    k_stats<<<BB*CIN, 256>>>(x0, x1);
    k_att<<<BB, 128>>>(fc_w, ln_g, ln_b, ch_w, ch_b, fl_w, fl_b,
                       sp_w, sp_b, kn_w, kn_b, mlp_w1, mlp_b1, mlp_w2, mlp_b2);
    k_agg<<<dim3(576, PB), 256>>>(weight);
    k_ftr<<<2*COUT, COUT>>>(fuse_w);
    k_wf <<<dim3(18, PB), 256>>>();
    k_tr <<<dim3(HW/128, CIN/32, PB), 256>>>(x0, x1);
    k_conv<<<dim3(HW/NPX, BB), NTHR, SMEM_BYTES>>>(fuse_b, out);
}

// round 13
// speedup vs baseline: 6.7674x; 1.7785x over previous
#include <cuda_runtime.h>
#include <cuda_fp16.h>
#include <math.h>

#define BB 8
#define CIN 128
#define COUT 128
#define KN 4
#define HH 160
#define WW 160
#define ATT 16
#define MID 32
#define HW (HH*WW)
#define IKK (CIN*9)
#define PB 16

#define NPX 128
#define NTHR 256
#define STG_BYTES 32768        // per stage: A 16KB + B 16KB (fp16, K-chunk 64)
#define SMEM_BYTES (2*STG_BYTES)

__device__ float g_gap0[BB*CIN];
__device__ float g_gap1[BB*CIN];
__device__ float g_fdmean[BB*CIN];
__device__ float g_fdmax[BB*CIN];
__device__ float g_ca[PB*CIN];
__device__ float g_fa[PB*COUT];
__device__ float g_sM[PB*9];
__device__ float g_ka[PB*KN];
__device__ float g_A[PB*COUT*IKK];
__device__ float g_fuseT[2*COUT*COUT];
// fp16 folded weights [pb][tap][oc][ic]
__device__ __align__(16) __half g_WfT[(size_t)PB*9*COUT*CIN];
__device__ __align__(16) __half g_xT[(size_t)PB*HW*CIN];   // fp16 NHWC

__device__ __forceinline__ float sigm(float x){ return 1.f/(1.f+expf(-x)); }
__device__ __forceinline__ unsigned smem_u32(const void* p){
    unsigned a;
    asm("{ .reg .u64 t; cvta.to.shared.u64 t, %1; cvt.u32.u64 %0, t; }" : "=r"(a) : "l"(p));
    return a;
}
__device__ __forceinline__ void mma_f16(float* c, const unsigned* a, const unsigned* b){
    asm volatile(
        "mma.sync.aligned.m16n8k16.row.col.f32.f16.f16.f32 "
        "{%0,%1,%2,%3}, {%4,%5,%6,%7}, {%8,%9}, {%0,%1,%2,%3};"
        : "+f"(c[0]), "+f"(c[1]), "+f"(c[2]), "+f"(c[3])
        : "r"(a[0]), "r"(a[1]), "r"(a[2]), "r"(a[3]), "r"(b[0]), "r"(b[1]));
}
__device__ __forceinline__ void ldsm4(unsigned* d, unsigned addr){
    asm volatile("ldmatrix.sync.aligned.m8n8.x4.shared.b16 {%0,%1,%2,%3}, [%4];"
        : "=r"(d[0]),"=r"(d[1]),"=r"(d[2]),"=r"(d[3]) : "r"(addr));
}
__device__ __forceinline__ void cp16(unsigned dst, const void* src, unsigned sz){
    asm volatile("cp.async.ca.shared.global [%0], [%1], 16, %2;"
        :: "r"(dst), "l"(src), "r"(sz) : "memory");
}

// ---------------- k_stats ----------------
__global__ __launch_bounds__(256) void k_stats(const float* __restrict__ x0,
                                               const float* __restrict__ x1){
    int bc = blockIdx.x;
    const float4* p0 = (const float4*)(x0 + (size_t)bc*HW);
    const float4* p1 = (const float4*)(x1 + (size_t)bc*HW);
    float s0=0.f, s1=0.f, mx=-3.0e38f;
    for (int i = threadIdx.x; i < HW/4; i += 256){
        float4 a = p0[i], b = p1[i];
        s0 += (a.x+a.y)+(a.z+a.w);
        s1 += (b.x+b.y)+(b.z+b.w);
        mx = fmaxf(mx, fmaxf(fmaxf(a.x-b.x,a.y-b.y), fmaxf(a.z-b.z,a.w-b.w)));
    }
    #pragma unroll
    for (int off=16; off; off>>=1){
        s0 += __shfl_down_sync(0xffffffffu, s0, off);
        s1 += __shfl_down_sync(0xffffffffu, s1, off);
        mx  = fmaxf(mx, __shfl_down_sync(0xffffffffu, mx, off));
    }
    __shared__ float r0[8], r1[8], rm[8];
    int w = threadIdx.x >> 5;
    if ((threadIdx.x & 31) == 0){ r0[w]=s0; r1[w]=s1; rm[w]=mx; }
    __syncthreads();
    if (threadIdx.x == 0){
        float S0=0.f, S1=0.f, M=-3.0e38f;
        #pragma unroll
        for (int i=0;i<8;++i){ S0+=r0[i]; S1+=r1[i]; M=fmaxf(M, rm[i]); }
        const float inv = 1.f/(float)HW;
        g_gap0[bc]=S0*inv; g_gap1[bc]=S1*inv; g_fdmean[bc]=(S0-S1)*inv; g_fdmax[bc]=M;
    }
}

// ---------------- k_att ----------------
__global__ __launch_bounds__(128) void k_att(
    const float* __restrict__ fc_w,  const float* __restrict__ ln_g,  const float* __restrict__ ln_b,
    const float* __restrict__ ch_w,  const float* __restrict__ ch_b,
    const float* __restrict__ fl_w,  const float* __restrict__ fl_b,
    const float* __restrict__ sp_w,  const float* __restrict__ sp_b,
    const float* __restrict__ kn_w,  const float* __restrict__ kn_b,
    const float* __restrict__ mlp_w1,const float* __restrict__ mlp_b1,
    const float* __restrict__ mlp_w2,const float* __restrict__ mlp_b2)
{
    int b = blockIdx.x, tid = threadIdx.x;
    __shared__ float gA[128], gB[128], yv[ATT], hs[MID], mfd[9], kl[KN];
    gA[tid] = g_fdmean[b*CIN + tid];
    gB[tid] = g_fdmax [b*CIN + tid];
    __syncthreads();
    if (tid < MID){
        float sa_ = mlp_b1[tid], sm_ = mlp_b1[tid];
        for (int c=0;c<CIN;++c){ float w = mlp_w1[tid*CIN+c]; sa_ += w*gA[c]; sm_ += w*gB[c]; }
        hs[tid] = fmaxf(sa_,0.f) + fmaxf(sm_,0.f);
    }
    __syncthreads();
    if (tid < 9){
        float z = 2.f*mlp_b2[tid];
        for (int t=0;t<MID;++t) z += mlp_w2[tid*MID+t]*hs[t];
        mfd[tid] = sigm(z);
    }
    for (int p=0;p<2;++p){
        __syncthreads();
        gA[tid] = (p ? g_gap1 : g_gap0)[b*CIN + tid];
        __syncthreads();
        if (tid < ATT){
            float v = 0.f;
            for (int c=0;c<CIN;++c) v += fc_w[tid*CIN+c]*gA[c];
            yv[tid] = v;
        }
        __syncthreads();
        if (tid == 0){
            float mu = 0.f;
            for (int j=0;j<ATT;++j) mu += yv[j];
            mu *= (1.f/ATT);
            float var = 0.f;
            for (int j=0;j<ATT;++j){ float d = yv[j]-mu; var += d*d; }
            var *= (1.f/ATT);
            float inv = rsqrtf(var + 1e-5f);
            for (int j=0;j<ATT;++j)
                yv[j] = fmaxf(0.f, (yv[j]-mu)*inv*ln_g[j] + ln_b[j]);
        }
        __syncthreads();
        {
            float ac = ch_b[tid], af = fl_b[tid];
            for (int j=0;j<ATT;++j){ ac += ch_w[tid*ATT+j]*yv[j]; af += fl_w[tid*ATT+j]*yv[j]; }
            g_ca[(p*BB+b)*CIN  + tid] = sigm(ac);
            g_fa[(p*BB+b)*COUT + tid] = sigm(af);
        }
        if (tid < 9){
            float s = sp_b[tid];
            for (int j=0;j<ATT;++j) s += sp_w[tid*ATT+j]*yv[j];
            g_sM[(p*BB+b)*9 + tid] = sigm(s)*mfd[tid];
        }
        if (tid < KN){
            float l = kn_b[tid];
            for (int j=0;j<ATT;++j) l += kn_w[tid*ATT+j]*yv[j];
            kl[tid] = l;
        }
        __syncthreads();
        if (tid == 0){
            float m = fmaxf(fmaxf(kl[0],kl[1]), fmaxf(kl[2],kl[3]));
            float e0=expf(kl[0]-m), e1=expf(kl[1]-m), e2=expf(kl[2]-m), e3=expf(kl[3]-m);
            float s = e0+e1+e2+e3;
            g_ka[(p*BB+b)*KN+0]=e0/s; g_ka[(p*BB+b)*KN+1]=e1/s;
            g_ka[(p*BB+b)*KN+2]=e2/s; g_ka[(p*BB+b)*KN+3]=e3/s;
        }
    }
}

// ---------------- k_agg ----------------
__global__ __launch_bounds__(256) void k_agg(const float* __restrict__ weight){
    int pb  = blockIdx.y;
    int idx = blockIdx.x*256 + threadIdx.x;
    int c   = idx / IKK;
    float k0=g_ka[pb*KN+0], k1=g_ka[pb*KN+1], k2=g_ka[pb*KN+2], k3=g_ka[pb*KN+3];
    const float* w = weight + idx;
    float acc = k0*w[0] + k1*w[COUT*IKK] + k2*w[2*COUT*IKK] + k3*w[3*COUT*IKK];
    g_A[pb*(COUT*IKK) + idx] = acc * g_fa[pb*COUT + c];
}

// ---------------- k_ftr ----------------
__global__ __launch_bounds__(128) void k_ftr(const float* __restrict__ fuse_w){
    int c = blockIdx.x, o = threadIdx.x;
    g_fuseT[c*COUT + o] = fuse_w[o*(2*COUT) + c];
}

// ---------------- k_wf : fuse-GEMM + scales -> fp16 [tap][oc][ic] ----------
__global__ __launch_bounds__(256) void k_wf(){
    int pb = blockIdx.y, p = pb >> 3;
    int nt = blockIdx.x;
    int tid = threadIdx.x;
    int to = tid & 15, tn = tid >> 4;
    __shared__ __align__(16) float Fs[16][128];
    __shared__ __align__(16) float As[16][64];
    float acc[8][4];
    #pragma unroll
    for (int o=0;o<8;++o)
        #pragma unroll
        for (int n=0;n<4;++n) acc[o][n]=0.f;
    const float* Abase = g_A + (size_t)pb*(COUT*IKK);
    for (int ck=0; ck<8; ++ck){
        __syncthreads();
        #pragma unroll
        for (int j=0;j<8;++j){
            int l = j*256 + tid; int o = l & 127, cc = l >> 7;
            Fs[cc][o] = g_fuseT[(p*COUT + ck*16 + cc)*COUT + o];
        }
        #pragma unroll
        for (int j=0;j<4;++j){
            int l = j*256 + tid; int nn = l & 63, cc = l >> 6;
            As[cc][nn] = Abase[(ck*16+cc)*IKK + nt*64 + nn];
        }
        __syncthreads();
        #pragma unroll
        for (int cc=0; cc<16; ++cc){
            float4 av = *(const float4*)&As[cc][tn*4];
            float a_[4] = {av.x, av.y, av.z, av.w};
            float4 f0 = *(const float4*)&Fs[cc][to*8];
            float4 f1 = *(const float4*)&Fs[cc][to*8+4];
            float f_[8] = {f0.x,f0.y,f0.z,f0.w, f1.x,f1.y,f1.z,f1.w};
            #pragma unroll
            for (int o=0;o<8;++o)
                #pragma unroll
                for (int n=0;n<4;++n)
                    acc[o][n] = fmaf(f_[o], a_[n], acc[o][n]);
        }
    }
    __half* Wbase = g_WfT + (size_t)pb*9*COUT*CIN;
    const float* cap = g_ca + pb*CIN;
    const float* sMp = g_sM + pb*9;
    #pragma unroll
    for (int n=0;n<4;++n){
        int ikk = nt*64 + tn*4 + n;
        int ic = ikk/9, tap = ikk - ic*9;
        float sc = cap[ic]*sMp[tap];
        #pragma unroll
        for (int o=0;o<8;++o){
            int oc = to*8 + o;
            Wbase[((size_t)tap*COUT + oc)*CIN + ic] = __float2half_rn(acc[o][n]*sc);
        }
    }
}

// ---------------- k_tr : NCHW fp32 -> NHWC fp16 ----------------
__global__ __launch_bounds__(256) void k_tr(const float* __restrict__ x0,
                                            const float* __restrict__ x1){
    int px0 = blockIdx.x*128, ic0 = blockIdx.y*32, z = blockIdx.z;
    const float* src = (z >= 8 ? x1 : x0) + ((size_t)(z&7)*CIN + ic0)*HW + px0;
    __shared__ float t[32][129];
    int tid = threadIdx.x, lane = tid & 31, w = tid >> 5;
    #pragma unroll
    for (int i=0;i<4;++i){
        int ic = w + i*8;
        float4 v = *(const float4*)(src + (size_t)ic*HW + lane*4);
        t[ic][lane*4+0]=v.x; t[ic][lane*4+1]=v.y; t[ic][lane*4+2]=v.z; t[ic][lane*4+3]=v.w;
    }
    __syncthreads();
    int px = tid >> 1, icg = (tid & 1)*16;
    __half* dst = g_xT + ((size_t)z*HW + px0 + px)*CIN + ic0 + icg;
    unsigned v[8];
    #pragma unroll
    for (int j=0;j<8;++j){
        __half2 h = __floats2half2_rn(t[icg+2*j][px], t[icg+2*j+1][px]);
        v[j] = *(unsigned*)&h;
    }
    *(uint4*)(dst)     = make_uint4(v[0],v[1],v[2],v[3]);
    *(uint4*)(dst + 8) = make_uint4(v[4],v[5],v[6],v[7]);
}

// ---------------- k_conv : fp16 mma.sync m16n8k16, K-chunk 64, 2-stage ------
// CTA 256 thr (8 warps), D[128 oc][128 px]; 2 CTAs/SM.
__global__ __launch_bounds__(NTHR, 2) void k_conv(const float* __restrict__ fuse_b,
                                                  float* __restrict__ out){
    extern __shared__ float dsm[];
    __shared__ float sBias[128];
    int b = blockIdx.y;
    int px0 = blockIdx.x*NPX;
    int tid = threadIdx.x;
    int lane = tid & 31, wid = tid >> 5;
    int wm = wid >> 2, wn = wid & 3;     // warp: 64 oc x 32 px (2 x 4 warps)
    int g = lane >> 2, tg = lane & 3;
    int sel = lane >> 3, r8 = lane & 7;
    int rowA = r8 + ((sel & 1) << 3), kselA = sel >> 1;
    int rowB = r8 + ((sel >> 1) << 3), kselB = sel & 1;
    if (tid < 128) sBias[tid] = fuse_b[tid];
    unsigned smem_base = smem_u32(dsm);

    // ldsm row bases (rows are 128B; XOR operand == r8)
    unsigned aoff[4], boff[2];
    #pragma unroll
    for (int mt=0;mt<4;++mt) aoff[mt] = (wm*64 + mt*16 + rowA)*128;
    #pragma unroll
    for (int q=0;q<2;++q)    boff[q] = 16384 + (wn*32 + q*16 + rowB)*128;

    // hoisted staging geometry (16B granules, 8 per 128B row)
    unsigned dstA[4]; int srcA[4];
    #pragma unroll
    for (int j=0;j<4;++j){
        int idx = j*NTHR + tid;
        int oc = idx>>3, c8 = idx&7;
        dstA[j] = oc*128 + ((c8 ^ (oc&7))<<4);
        srcA[j] = oc*CIN + c8*8;           // half units
    }
    unsigned dstB[4]; int srcB[4]; unsigned bmask[4];
    #pragma unroll
    for (int j=0;j<4;++j){
        int idx = j*NTHR + tid;
        int px = idx>>3, c8 = idx&7;
        dstB[j] = 16384 + px*128 + ((c8 ^ (px&7))<<4);
        int pg = px0 + px;
        int y = pg/WW, x = pg - y*WW;
        srcB[j] = (y*WW + x - WW - 1)*CIN + c8*8;
        unsigned m = 0;
        #pragma unroll
        for (int tap=0;tap<9;++tap){
            int dy = tap/3, dx = tap - dy*3;
            bool ok = ((unsigned)(y+dy-1) < (unsigned)HH) && ((unsigned)(x+dx-1) < (unsigned)WW);
            m |= (ok ? 1u : 0u) << tap;
        }
        bmask[j] = m;
    }

    float acc[4][4][4];
    #pragma unroll
    for (int mt=0;mt<4;++mt)
        #pragma unroll
        for (int nt=0;nt<4;++nt)
            #pragma unroll
            for (int e=0;e<4;++e) acc[mt][nt][e]=0.f;

    auto stage_issue = [&](int c, int slot){
        int p = (c>=18) ? 1 : 0;
        int rr = c - p*18;
        int tap = rr>>1, ich = rr&1;
        int dy = tap/3, dx = tap - dy*3;
        int pb = p*BB + b;
        unsigned sbase = smem_base + slot*STG_BYTES;
        const __half* Ab = g_WfT + ((size_t)pb*9 + tap)*COUT*CIN + ich*64;
        #pragma unroll
        for (int j=0;j<4;++j)
            cp16(sbase + dstA[j], Ab + srcA[j], 16);
        const __half* Bb = g_xT + (size_t)pb*HW*CIN + (dy*WW + dx)*CIN + ich*64;
        unsigned tb = 1u << tap;
        #pragma unroll
        for (int j=0;j<4;++j)
            cp16(sbase + dstB[j], Bb + srcB[j], (bmask[j] & tb) ? 16u : 0u);
        asm volatile("cp.async.commit_group;" ::: "memory");
    };

    stage_issue(0, 0);
    stage_issue(1, 1);
    for (int c=0;c<36;++c){
        if (c < 34) asm volatile("cp.async.wait_group 1;" ::: "memory");
        else        asm volatile("cp.async.wait_group 0;" ::: "memory");
        __syncthreads();
        unsigned base = smem_base + (c&1)*STG_BYTES;
        #pragma unroll
        for (int ks=0;ks<4;++ks){
            unsigned kA = (unsigned)(((ks*2 + kselA) ^ r8) << 4);
            unsigned kB = (unsigned)(((ks*2 + kselB) ^ r8) << 4);
            unsigned af[4][4], bf[2][4];
            #pragma unroll
            for (int mt=0;mt<4;++mt) ldsm4(af[mt], base + aoff[mt] + kA);
            #pragma unroll
            for (int q=0;q<2;++q)    ldsm4(bf[q],  base + boff[q] + kB);
            #pragma unroll
            for (int mt=0;mt<4;++mt)
                #pragma unroll
                for (int nt=0;nt<4;++nt)
                    mma_f16(acc[mt][nt], af[mt], &bf[nt>>1][(nt&1)*2]);
        }
        __syncthreads();
        if (c+2 < 36) stage_issue(c+2, c&1);
    }

    #pragma unroll
    for (int mt=0;mt<4;++mt){
        int oc = wm*64 + mt*16 + g;
        float b0 = sBias[oc], b1 = sBias[oc+8];
        #pragma unroll
        for (int nt=0;nt<4;++nt){
            int n = wn*32 + nt*8 + 2*tg;
            float* o0 = out + ((size_t)b*COUT + oc)*HW + px0 + n;
            float* o1 = out + ((size_t)b*COUT + oc + 8)*HW + px0 + n;
            *(float2*)o0 = make_float2(acc[mt][nt][0]+b0, acc[mt][nt][1]+b0);
            *(float2*)o1 = make_float2(acc[mt][nt][2]+b1, acc[mt][nt][3]+b1);
        }
    }
}

// ---------------- launch ----------------
extern "C" void kernel_launch(void* const* d_in, const int* in_sizes, int n_in,
                              void* d_out, int out_size){
    const float* x0     = (const float*)d_in[0];
    const float* x1     = (const float*)d_in[1];
    const float* fc_w   = (const float*)d_in[2];
    const float* ln_g   = (const float*)d_in[3];
    const float* ln_b   = (const float*)d_in[4];
    const float* ch_w   = (const float*)d_in[5];
    const float* ch_b   = (const float*)d_in[6];
    const float* fl_w   = (const float*)d_in[7];
    const float* fl_b   = (const float*)d_in[8];
    const float* sp_w   = (const float*)d_in[9];
    const float* sp_b   = (const float*)d_in[10];
    const float* kn_w   = (const float*)d_in[11];
    const float* kn_b   = (const float*)d_in[12];
    const float* weight = (const float*)d_in[13];
    const float* mlp_w1 = (const float*)d_in[14];
    const float* mlp_b1 = (const float*)d_in[15];
    const float* mlp_w2 = (const float*)d_in[16];
    const float* mlp_b2 = (const float*)d_in[17];
    const float* fuse_w = (const float*)d_in[18];
    const float* fuse_b = (const float*)d_in[19];
    float* out = (float*)d_out;

    cudaFuncSetAttribute(k_conv, cudaFuncAttributeMaxDynamicSharedMemorySize, SMEM_BYTES);

    k_stats<<<BB*CIN, 256>>>(x0, x1);
    k_att<<<BB, 128>>>(fc_w, ln_g, ln_b, ch_w, ch_b, fl_w, fl_b,
                       sp_w, sp_b, kn_w, kn_b, mlp_w1, mlp_b1, mlp_w2, mlp_b2);
    k_agg<<<dim3(576, PB), 256>>>(weight);
    k_ftr<<<2*COUT, COUT>>>(fuse_w);
    k_wf <<<dim3(18, PB), 256>>>();
    k_tr <<<dim3(HW/128, CIN/32, PB), 256>>>(x0, x1);
    k_conv<<<dim3(HW/NPX, BB), NTHR, SMEM_BYTES>>>(fuse_b, out);
}